// round 3
// baseline (speedup 1.0000x reference)
#include <cuda_runtime.h>
#include <math.h>

#define BB 4
#define NN 256
#define DD 128
#define NROWS (BB*NN)            // 1024
#define EROWS (BB*NN*NN)         // 262144
#define EPSF 1e-5f

// ---------------- scratch (static device globals; no runtime allocation) ----
__device__ float g_Ah[NROWS*DD];
__device__ float g_Bh[NROWS*DD];
__device__ float g_Uh[NROWS*DD];
__device__ float g_Vh[NROWS*DD];
__device__ float g_WcT[DD*DD];                 // wC transposed: [k][col]
__device__ float g_gi[(size_t)EROWS*DD];       // gate_input scratch, 134 MB
__device__ float g_agg[NROWS*DD];
__device__ float g_hact[NROWS*DD];
__device__ float g_esum[DD];
__device__ float g_esq[DD];
__device__ float g_nsum[DD];
__device__ float g_nsq[DD];
__device__ float g_par[4*DD];   // [escale | eshift | nscale | nshift]

// ---------------- K0: zero accumulators + transpose wC ---------------------
__global__ void k_prep(const float* __restrict__ wC) {
    int idx = blockIdx.x * blockDim.x + threadIdx.x;   // 131072 threads
    if (idx < NROWS*DD) g_agg[idx] = 0.f;
    if (idx < DD*DD) {
        int k = idx >> 7, col = idx & 127;
        g_WcT[idx] = wC[col*DD + k];
    }
    if (idx < DD) {
        g_esum[idx] = 0.f; g_esq[idx] = 0.f;
        g_nsum[idx] = 0.f; g_nsq[idx] = 0.f;
    }
}

// ---------------- K1: Ah/Bh/Uh/Vh = h @ W^T ---------------------------------
__global__ __launch_bounds__(128) void k_node_gemm(
    const float* __restrict__ h,
    const float* __restrict__ wA, const float* __restrict__ wB,
    const float* __restrict__ wU, const float* __restrict__ wV)
{
    __shared__ float sH[16*DD];
    const float* W; float* out;
    switch (blockIdx.y) {
        case 0:  W = wA; out = g_Ah; break;
        case 1:  W = wB; out = g_Bh; break;
        case 2:  W = wU; out = g_Uh; break;
        default: W = wV; out = g_Vh; break;
    }
    const int r0 = blockIdx.x * 16;
    const int t  = threadIdx.x;
    for (int idx = t; idx < 16*DD; idx += 128) sH[idx] = h[r0*DD + idx];
    __syncthreads();

    float acc[16];
    #pragma unroll
    for (int r = 0; r < 16; r++) acc[r] = 0.f;

    const float4* Wr  = (const float4*)(W + t*DD);   // this thread's W row
    const float4* sH4 = (const float4*)sH;
    #pragma unroll 8
    for (int kq = 0; kq < 32; kq++) {
        float4 w = Wr[kq];
        #pragma unroll
        for (int r = 0; r < 16; r++) {
            float4 hv = sH4[r*32 + kq];
            acc[r] += w.x*hv.x + w.y*hv.y + w.z*hv.z + w.w*hv.w;
        }
    }
    #pragma unroll
    for (int r = 0; r < 16; r++) out[(r0 + r)*DD + t] = acc[r];
}

// ---------------- K2: fused edge pass ---------------------------------------
// Per block: 64 rows (fixed b,i; 64 consecutive j) x 128 cols.
// gate_input = e@wC^T + Ah[i] + Bh[j]  -> store to g_gi
// agg[b,i,:] += sigmoid(gi) * Vh[j,:]  (smem reduce -> global atomics)
// edge BN sum / sumsq                  (smem reduce -> global atomics)
__global__ __launch_bounds__(256) void k_edge(const float* __restrict__ e)
{
    __shared__ float sE[64*32];     // E tile for one k-chunk
    __shared__ float sW[32*DD];     // WcT tile [k][col]
    __shared__ float sAh[DD];
    __shared__ float sRed[3*DD];    // agg | sum | sumsq

    const int t  = threadIdx.x;
    const int r0 = blockIdx.x * 64;
    const int b  = r0 / (NN*NN);
    const int rm = r0 % (NN*NN);
    const int i  = rm / NN;
    const int j0 = rm % NN;

    if (t < DD) {
        sAh[t] = g_Ah[(b*NN + i)*DD + t];
        sRed[t] = 0.f; sRed[DD + t] = 0.f; sRed[2*DD + t] = 0.f;
    }

    const int tc = t & 15;      // col group (8 cols)
    const int tr = t >> 4;      // row group (4 rows)

    float c[4][8];
    #pragma unroll
    for (int rr = 0; rr < 4; rr++)
        #pragma unroll
        for (int cc = 0; cc < 8; cc++) c[rr][cc] = 0.f;

    const float4* e4   = (const float4*)e;
    const float4* Wt4  = (const float4*)g_WcT;
    float4* sE4 = (float4*)sE;
    float4* sW4 = (float4*)sW;

    for (int kb = 0; kb < DD; kb += 32) {
        __syncthreads();
        // E tile: 64 rows x 32 k-values (coalesced float4)
        {
            int k4   = t & 7;           // which float4 in the 32-k slab
            int rowa = t >> 3;          // 0..31
            sE4[rowa*8 + k4]        = e4[(size_t)(r0 + rowa)*32 + (kb >> 2) + k4];
            sE4[(rowa + 32)*8 + k4] = e4[(size_t)(r0 + rowa + 32)*32 + (kb >> 2) + k4];
        }
        // W tile: 32 k-rows x 128 cols (coalesced)
        #pragma unroll
        for (int q = 0; q < 4; q++) {
            int idx = t + 256*q;        // 0..1023 float4s
            sW4[idx] = Wt4[(size_t)kb*32 + idx];
        }
        __syncthreads();

        #pragma unroll
        for (int k = 0; k < 32; k++) {
            float4 w0 = sW4[k*32 + tc*2];
            float4 w1 = sW4[k*32 + tc*2 + 1];
            #pragma unroll
            for (int rr = 0; rr < 4; rr++) {
                float a = sE[(tr*4 + rr)*32 + k];
                c[rr][0] += a*w0.x; c[rr][1] += a*w0.y;
                c[rr][2] += a*w0.z; c[rr][3] += a*w0.w;
                c[rr][4] += a*w1.x; c[rr][5] += a*w1.y;
                c[rr][6] += a*w1.z; c[rr][7] += a*w1.w;
            }
        }
    }
    __syncthreads();

    // epilogue
    float ah[8];
    #pragma unroll
    for (int cc = 0; cc < 8; cc++) ah[cc] = sAh[tc*8 + cc];

    float pa[8], ps[8], pq[8];
    #pragma unroll
    for (int cc = 0; cc < 8; cc++) { pa[cc] = 0.f; ps[cc] = 0.f; pq[cc] = 0.f; }

    #pragma unroll
    for (int rr = 0; rr < 4; rr++) {
        const int j  = j0 + tr*4 + rr;
        const int nb = (b*NN + j)*DD + tc*8;
        float4 bh0 = *(const float4*)&g_Bh[nb];
        float4 bh1 = *(const float4*)&g_Bh[nb + 4];
        float4 vh0 = *(const float4*)&g_Vh[nb];
        float4 vh1 = *(const float4*)&g_Vh[nb + 4];

        float gi[8];
        gi[0] = c[rr][0] + ah[0] + bh0.x;
        gi[1] = c[rr][1] + ah[1] + bh0.y;
        gi[2] = c[rr][2] + ah[2] + bh0.z;
        gi[3] = c[rr][3] + ah[3] + bh0.w;
        gi[4] = c[rr][4] + ah[4] + bh1.x;
        gi[5] = c[rr][5] + ah[5] + bh1.y;
        gi[6] = c[rr][6] + ah[6] + bh1.z;
        gi[7] = c[rr][7] + ah[7] + bh1.w;

        size_t gb = ((size_t)(r0 + tr*4 + rr))*DD + tc*8;
        *(float4*)&g_gi[gb]     = make_float4(gi[0], gi[1], gi[2], gi[3]);
        *(float4*)&g_gi[gb + 4] = make_float4(gi[4], gi[5], gi[6], gi[7]);

        float vh[8] = {vh0.x, vh0.y, vh0.z, vh0.w, vh1.x, vh1.y, vh1.z, vh1.w};
        #pragma unroll
        for (int cc = 0; cc < 8; cc++) {
            float x = gi[cc];
            ps[cc] += x;
            pq[cc] += x*x;
            float s = 1.0f / (1.0f + __expf(-x));
            pa[cc] += s * vh[cc];
        }
    }
    #pragma unroll
    for (int cc = 0; cc < 8; cc++) {
        atomicAdd(&sRed[tc*8 + cc],        pa[cc]);
        atomicAdd(&sRed[DD + tc*8 + cc],   ps[cc]);
        atomicAdd(&sRed[2*DD + tc*8 + cc], pq[cc]);
    }
    __syncthreads();
    if (t < DD) {
        atomicAdd(&g_agg[(b*NN + i)*DD + t], sRed[t]);
        atomicAdd(&g_esum[t], sRed[DD + t]);
        atomicAdd(&g_esq[t],  sRed[2*DD + t]);
    }
}

// ---------------- K3: h_act = relu(Uh + agg) + node BN stats ----------------
// 32 blocks x 32 rows each; smem reduce -> 128 atomics per block per stat.
__global__ __launch_bounds__(256) void k_node_act() {
    __shared__ float sSum[2*DD], sSq[2*DD];
    const int t = threadIdx.x;
    const int c = t & (DD - 1);
    const int half = t >> 7;            // 0 or 1
    const int r0 = blockIdx.x * 32;
    float psum = 0.f, psq = 0.f;
    for (int r = half; r < 32; r += 2) {
        int idx = (r0 + r)*DD + c;
        float v = fmaxf(g_Uh[idx] + g_agg[idx], 0.f);
        g_hact[idx] = v;
        psum += v; psq += v*v;
    }
    sSum[t] = psum; sSq[t] = psq;
    __syncthreads();
    if (t < DD) {
        atomicAdd(&g_nsum[t], sSum[t] + sSum[t + DD]);
        atomicAdd(&g_nsq[t],  sSq[t]  + sSq[t + DD]);
    }
}

// ---------------- K4: finalize BN scale/shift --------------------------------
__global__ void k_stats(const float* __restrict__ gE, const float* __restrict__ bE,
                        const float* __restrict__ gN, const float* __restrict__ bN) {
    int c = threadIdx.x;
    if (c >= DD) return;
    const float cntE = (float)EROWS, cntN = (float)NROWS;
    float em = g_esum[c] / cntE;
    float ev = g_esq[c] / cntE - em*em;
    float ei = rsqrtf(ev + EPSF);
    float esc = ei * gE[c];
    g_par[c]      = esc;
    g_par[DD + c] = bE[c] - em*esc;

    float nm = g_nsum[c] / cntN;
    float nv = g_nsq[c] / cntN - nm*nm;
    float ni = rsqrtf(nv + EPSF);
    float nsc = ni * gN[c];
    g_par[2*DD + c] = nsc;
    g_par[3*DD + c] = bN[c] - nm*nsc;
}

// ---------------- K5: h_new --------------------------------------------------
__global__ void k_hout(const float* __restrict__ h, float* __restrict__ out) {
    int idx = blockIdx.x * blockDim.x + threadIdx.x;
    if (idx >= NROWS*DD) return;
    int c = idx & (DD - 1);
    out[idx] = g_hact[idx] * g_par[2*DD + c] + g_par[3*DD + c] + h[idx];
}

// ---------------- K6: e_new (streaming, float4) ------------------------------
__global__ void k_eout(const float* __restrict__ e, float* __restrict__ out) {
    size_t i = (size_t)blockIdx.x * blockDim.x + threadIdx.x;  // float4 index
    const size_t total4 = (size_t)EROWS * DD / 4;
    if (i >= total4) return;
    const float4* gi4 = (const float4*)g_gi;
    const float4* e4  = (const float4*)e;
    const float4* sc4 = (const float4*)g_par;          // escale
    const float4* sh4 = (const float4*)(g_par + DD);   // eshift
    int cq = (int)(i & 31);
    float4 s  = sc4[cq];
    float4 sh = sh4[cq];
    float4 g  = gi4[i];
    float4 ev = e4[i];
    float4 r;
    r.x = fmaxf(g.x*s.x + sh.x, 0.f) + ev.x;
    r.y = fmaxf(g.y*s.y + sh.y, 0.f) + ev.y;
    r.z = fmaxf(g.z*s.z + sh.z, 0.f) + ev.z;
    r.w = fmaxf(g.w*s.w + sh.w, 0.f) + ev.w;
    ((float4*)out)[i] = r;
}

// ---------------- launch -----------------------------------------------------
extern "C" void kernel_launch(void* const* d_in, const int* in_sizes, int n_in,
                              void* d_out, int out_size) {
    const float* h  = (const float*)d_in[0];
    const float* e  = (const float*)d_in[1];
    const float* wA = (const float*)d_in[2];
    const float* wB = (const float*)d_in[3];
    const float* wU = (const float*)d_in[4];
    const float* wV = (const float*)d_in[5];
    const float* wC = (const float*)d_in[6];
    const float* gN = (const float*)d_in[7];
    const float* bN = (const float*)d_in[8];
    const float* gE = (const float*)d_in[9];
    const float* bE = (const float*)d_in[10];
    float* out = (float*)d_out;

    k_prep<<<512, 256>>>(wC);
    k_node_gemm<<<dim3(NROWS/16, 4), 128>>>(h, wA, wB, wU, wV);
    k_edge<<<EROWS/64, 256>>>(e);
    k_node_act<<<32, 256>>>();
    k_stats<<<1, 128>>>(gE, bE, gN, bN);
    k_hout<<<NROWS*DD/256, 256>>>(h, out);
    k_eout<<<(EROWS*DD/4)/256, 256>>>(e, out + NROWS*DD);
}

// round 6
// speedup vs baseline: 1.3362x; 1.3362x over previous
#include <cuda_runtime.h>
#include <cuda_bf16.h>
#include <stdint.h>
#include <math.h>

#define BB 4
#define NN 256
#define DD 128
#define NROWS (BB*NN)            // 1024
#define EROWS (BB*NN*NN)         // 262144
#define EPSF 1e-5f

// ---------------- scratch (static device globals; no runtime allocation) ----
__device__ float g_Ah[NROWS*DD];
__device__ float g_Bh[NROWS*DD];
__device__ float g_Uh[NROWS*DD];
__device__ float g_Vh[NROWS*DD];
__device__ __nv_bfloat16 g_WB[2][DD][DD];      // wC rows as bf16 [hi|lo], B(k,n)=wC[n][k]
__device__ float g_gi[(size_t)EROWS*DD];       // gate_input scratch, 134 MB
__device__ float g_agg[NROWS*DD];
__device__ float g_hact[NROWS*DD];
__device__ float g_esum[DD];
__device__ float g_esq[DD];
__device__ float g_nsum[DD];
__device__ float g_nsq[DD];
__device__ float g_par[4*DD];   // [escale | eshift | nscale | nshift]

// SMEM layout for k_edge (dynamic):
// A: 2 segs x [128 rows][136 bf16]  (pitch 272 B, seg stride 34816 B)
// B: 2 segs x [128 n   ][136 bf16]
#define PITCH   272
#define SEG     34816
#define OFF_A   0
#define OFF_B   69632
#define OFF_AH  139264
#define OFF_RED 139776
#define SMEM_SZ 141312

// ---------------- K0: zero accumulators + build bf16 hi/lo W ---------------
__global__ void k_prep(const float* __restrict__ wC) {
    int idx = blockIdx.x * blockDim.x + threadIdx.x;   // 131072 threads
    if (idx < NROWS*DD) g_agg[idx] = 0.f;
    if (idx < DD) {
        g_esum[idx] = 0.f; g_esq[idx] = 0.f;
        g_nsum[idx] = 0.f; g_nsq[idx] = 0.f;
    }
    if (idx < DD*DD) {
        int n = idx >> 7, k = idx & 127;
        float x = wC[idx];
        __nv_bfloat16 hi = __float2bfloat16(x);
        __nv_bfloat16 lo = __float2bfloat16(x - __bfloat162float(hi));
        g_WB[0][n][k] = hi;
        g_WB[1][n][k] = lo;
    }
}

// ---------------- K1: Ah/Bh/Uh/Vh = h @ W^T ---------------------------------
__global__ __launch_bounds__(128) void k_node_gemm(
    const float* __restrict__ h,
    const float* __restrict__ wA, const float* __restrict__ wB,
    const float* __restrict__ wU, const float* __restrict__ wV)
{
    __shared__ float sH[16*DD];
    const float* W; float* out;
    switch (blockIdx.y) {
        case 0:  W = wA; out = g_Ah; break;
        case 1:  W = wB; out = g_Bh; break;
        case 2:  W = wU; out = g_Uh; break;
        default: W = wV; out = g_Vh; break;
    }
    const int r0 = blockIdx.x * 16;
    const int t  = threadIdx.x;
    for (int idx = t; idx < 16*DD; idx += 128) sH[idx] = h[r0*DD + idx];
    __syncthreads();

    float acc[16];
    #pragma unroll
    for (int r = 0; r < 16; r++) acc[r] = 0.f;

    const float4* Wr  = (const float4*)(W + t*DD);
    const float4* sH4 = (const float4*)sH;
    #pragma unroll 8
    for (int kq = 0; kq < 32; kq++) {
        float4 w = Wr[kq];
        #pragma unroll
        for (int r = 0; r < 16; r++) {
            float4 hv = sH4[r*32 + kq];
            acc[r] += w.x*hv.x + w.y*hv.y + w.z*hv.z + w.w*hv.w;
        }
    }
    #pragma unroll
    for (int r = 0; r < 16; r++) out[(r0 + r)*DD + t] = acc[r];
}

// ---------------- K2: HMMA edge pass ----------------------------------------
// Per CTA: 128 edge rows (fixed b,i; j0..j0+127) x 128 cols, K=128.
// gi = e@wC^T via bf16 hi/lo split (3 products, fp32 accum) + Ah[i] + Bh[j]
//   -> g_gi, plus column reductions (edge-BN stats, agg = sum_j sigmoid*Vh).
__global__ __launch_bounds__(256, 1) void k_edge_mma(const float* __restrict__ e)
{
    extern __shared__ char smem[];
    const int t = threadIdx.x;
    const int w = t >> 5, l = t & 31;
    const int g = l >> 2, tq = l & 3;
    const int r0 = blockIdx.x * 128;
    const int b  = r0 >> 16;
    const int rm = r0 & 65535;
    const int i  = rm >> 8;
    const int j0 = rm & 255;

    float* red = (float*)(smem + OFF_RED);
    if (t < DD) {
        ((float*)(smem + OFF_AH))[t] = g_Ah[(b*NN + i)*DD + t];
        red[t] = 0.f; red[DD + t] = 0.f; red[2*DD + t] = 0.f;
    }

    // --- stage A: e tile fp32 -> bf16 hi/lo --------------------------------
    {
        const float4* e4 = (const float4*)e;
        char* sA = smem + OFF_A;
        #pragma unroll 4
        for (int rr = 0; rr < 16; rr++) {
            int r = w*16 + rr;
            float4 v = e4[(size_t)(r0 + r)*32 + l];
            __nv_bfloat162 h0, h1, l0, l1;
            h0.x = __float2bfloat16(v.x); h0.y = __float2bfloat16(v.y);
            h1.x = __float2bfloat16(v.z); h1.y = __float2bfloat16(v.w);
            l0.x = __float2bfloat16(v.x - __bfloat162float(h0.x));
            l0.y = __float2bfloat16(v.y - __bfloat162float(h0.y));
            l1.x = __float2bfloat16(v.z - __bfloat162float(h1.x));
            l1.y = __float2bfloat16(v.w - __bfloat162float(h1.y));
            uint32_t off = (uint32_t)(r*PITCH + l*8);
            *(uint2*)(sA + off)       = make_uint2(*(uint32_t*)&h0, *(uint32_t*)&h1);
            *(uint2*)(sA + SEG + off) = make_uint2(*(uint32_t*)&l0, *(uint32_t*)&l1);
        }
    }
    // --- stage B: copy g_WB (both segs) ------------------------------------
    {
        const uint4* src = (const uint4*)g_WB;   // [2][128][16] uint4
        #pragma unroll
        for (int q = 0; q < 16; q++) {
            int idx = t + q*256;                 // 0..4095
            int seg = idx >> 11;
            int rem = idx & 2047;
            int r = rem >> 4, c = rem & 15;
            *(uint4*)(smem + OFF_B + seg*SEG + r*PITCH + c*16) = src[idx];
        }
    }
    __syncthreads();

    // --- MMA mainloop -------------------------------------------------------
    const int wr = w & 3;      // row quarter:  rows wr*32 .. +31
    const int wc = w >> 2;     // col half:     cols wc*64 .. +63
    float acc[2][8][4];
    #pragma unroll
    for (int mt = 0; mt < 2; mt++)
        #pragma unroll
        for (int nt = 0; nt < 8; nt++)
            #pragma unroll
            for (int q = 0; q < 4; q++) acc[mt][nt][q] = 0.f;

    #pragma unroll
    for (int sgi = 0; sgi < 3; sgi++) {
        const char* pA = smem + OFF_A + ((sgi == 2) ? SEG : 0);
        const char* pB = smem + OFF_B + ((sgi == 1) ? SEG : 0);
        #pragma unroll
        for (int ks = 0; ks < 8; ks++) {
            const int kb = ks*32 + tq*4;         // byte offset of this lane's k pair
            uint32_t a[2][4];
            #pragma unroll
            for (int mt = 0; mt < 2; mt++) {
                const char* pr = pA + (wr*32 + mt*16 + g)*PITCH + kb;
                a[mt][0] = *(const uint32_t*)(pr);
                a[mt][1] = *(const uint32_t*)(pr + 8*PITCH);
                a[mt][2] = *(const uint32_t*)(pr + 16);
                a[mt][3] = *(const uint32_t*)(pr + 8*PITCH + 16);
            }
            #pragma unroll
            for (int nt = 0; nt < 8; nt++) {
                const char* pb = pB + (wc*64 + nt*8 + g)*PITCH + kb;
                uint32_t b0 = *(const uint32_t*)pb;
                uint32_t b1 = *(const uint32_t*)(pb + 16);
                #pragma unroll
                for (int mt = 0; mt < 2; mt++) {
                    asm volatile(
                        "mma.sync.aligned.m16n8k16.row.col.f32.bf16.bf16.f32 "
                        "{%0,%1,%2,%3}, {%4,%5,%6,%7}, {%8,%9}, {%0,%1,%2,%3};"
                        : "+f"(acc[mt][nt][0]), "+f"(acc[mt][nt][1]),
                          "+f"(acc[mt][nt][2]), "+f"(acc[mt][nt][3])
                        : "r"(a[mt][0]), "r"(a[mt][1]), "r"(a[mt][2]), "r"(a[mt][3]),
                          "r"(b0), "r"(b1));
                }
            }
        }
    }

    // --- epilogue -----------------------------------------------------------
    const float* ah = (const float*)(smem + OFF_AH);
    #pragma unroll
    for (int nt = 0; nt < 8; nt++) {
        const int C = wc*64 + nt*8 + 2*tq;
        const float ah0 = ah[C], ah1 = ah[C+1];
        float s1 = 0.f, s2 = 0.f, sv = 0.f;
        float u1 = 0.f, u2 = 0.f, uv = 0.f;
        #pragma unroll
        for (int mt = 0; mt < 2; mt++) {
            #pragma unroll
            for (int hf = 0; hf < 2; hf++) {
                const int rloc = wr*32 + mt*16 + g + hf*8;
                const size_t nb = (size_t)(b*NN + j0 + rloc)*DD + C;
                float2 bh = *(const float2*)&g_Bh[nb];
                float2 vh = *(const float2*)&g_Vh[nb];
                float gi0 = acc[mt][nt][hf*2+0] + ah0 + bh.x;
                float gi1 = acc[mt][nt][hf*2+1] + ah1 + bh.y;
                *(float2*)&g_gi[(size_t)(r0 + rloc)*DD + C] = make_float2(gi0, gi1);
                s1 += gi0; s2 += gi0*gi0; sv += vh.x / (1.0f + __expf(-gi0));
                u1 += gi1; u2 += gi1*gi1; uv += vh.y / (1.0f + __expf(-gi1));
            }
        }
        // reduce over the 8 row-groups (lanes differing in bits 2..4)
        #pragma unroll
        for (int m = 16; m >= 4; m >>= 1) {
            s1 += __shfl_xor_sync(0xFFFFFFFFu, s1, m);
            s2 += __shfl_xor_sync(0xFFFFFFFFu, s2, m);
            sv += __shfl_xor_sync(0xFFFFFFFFu, sv, m);
            u1 += __shfl_xor_sync(0xFFFFFFFFu, u1, m);
            u2 += __shfl_xor_sync(0xFFFFFFFFu, u2, m);
            uv += __shfl_xor_sync(0xFFFFFFFFu, uv, m);
        }
        if (g == 0) {
            atomicAdd(&red[C],            s1);
            atomicAdd(&red[C + 1],        u1);
            atomicAdd(&red[DD + C],       s2);
            atomicAdd(&red[DD + C + 1],   u2);
            atomicAdd(&red[2*DD + C],     sv);
            atomicAdd(&red[2*DD + C + 1], uv);
        }
    }
    __syncthreads();
    if (t < DD) {
        atomicAdd(&g_esum[t], red[t]);
        atomicAdd(&g_esq[t],  red[DD + t]);
        atomicAdd(&g_agg[(b*NN + i)*DD + t], red[2*DD + t]);
    }
}

// ---------------- K3: h_act = relu(Uh + agg) + node BN stats ----------------
__global__ __launch_bounds__(256) void k_node_act() {
    __shared__ float sSum[2*DD], sSq[2*DD];
    const int t = threadIdx.x;
    const int c = t & (DD - 1);
    const int half = t >> 7;
    const int r0 = blockIdx.x * 32;
    float psum = 0.f, psq = 0.f;
    for (int r = half; r < 32; r += 2) {
        int idx = (r0 + r)*DD + c;
        float v = fmaxf(g_Uh[idx] + g_agg[idx], 0.f);
        g_hact[idx] = v;
        psum += v; psq += v*v;
    }
    sSum[t] = psum; sSq[t] = psq;
    __syncthreads();
    if (t < DD) {
        atomicAdd(&g_nsum[t], sSum[t] + sSum[t + DD]);
        atomicAdd(&g_nsq[t],  sSq[t]  + sSq[t + DD]);
    }
}

// ---------------- K4: finalize BN scale/shift --------------------------------
__global__ void k_stats(const float* __restrict__ gE, const float* __restrict__ bE,
                        const float* __restrict__ gN, const float* __restrict__ bN) {
    int c = threadIdx.x;
    if (c >= DD) return;
    const float cntE = (float)EROWS, cntN = (float)NROWS;
    float em = g_esum[c] / cntE;
    float ev = g_esq[c] / cntE - em*em;
    float ei = rsqrtf(ev + EPSF);
    float esc = ei * gE[c];
    g_par[c]      = esc;
    g_par[DD + c] = bE[c] - em*esc;

    float nm = g_nsum[c] / cntN;
    float nv = g_nsq[c] / cntN - nm*nm;
    float ni = rsqrtf(nv + EPSF);
    float nsc = ni * gN[c];
    g_par[2*DD + c] = nsc;
    g_par[3*DD + c] = bN[c] - nm*nsc;
}

// ---------------- K5: h_new --------------------------------------------------
__global__ void k_hout(const float* __restrict__ h, float* __restrict__ out) {
    int idx = blockIdx.x * blockDim.x + threadIdx.x;
    if (idx >= NROWS*DD) return;
    int c = idx & (DD - 1);
    out[idx] = g_hact[idx] * g_par[2*DD + c] + g_par[3*DD + c] + h[idx];
}

// ---------------- K6: e_new (streaming, float4) ------------------------------
__global__ void k_eout(const float* __restrict__ e, float* __restrict__ out) {
    size_t i = (size_t)blockIdx.x * blockDim.x + threadIdx.x;
    const size_t total4 = (size_t)EROWS * DD / 4;
    if (i >= total4) return;
    const float4* gi4 = (const float4*)g_gi;
    const float4* e4  = (const float4*)e;
    const float4* sc4 = (const float4*)g_par;
    const float4* sh4 = (const float4*)(g_par + DD);
    int cq = (int)(i & 31);
    float4 s  = sc4[cq];
    float4 sh = sh4[cq];
    float4 g  = gi4[i];
    float4 ev = e4[i];
    float4 r;
    r.x = fmaxf(g.x*s.x + sh.x, 0.f) + ev.x;
    r.y = fmaxf(g.y*s.y + sh.y, 0.f) + ev.y;
    r.z = fmaxf(g.z*s.z + sh.z, 0.f) + ev.z;
    r.w = fmaxf(g.w*s.w + sh.w, 0.f) + ev.w;
    ((float4*)out)[i] = r;
}

// ---------------- launch -----------------------------------------------------
extern "C" void kernel_launch(void* const* d_in, const int* in_sizes, int n_in,
                              void* d_out, int out_size) {
    const float* h  = (const float*)d_in[0];
    const float* e  = (const float*)d_in[1];
    const float* wA = (const float*)d_in[2];
    const float* wB = (const float*)d_in[3];
    const float* wU = (const float*)d_in[4];
    const float* wV = (const float*)d_in[5];
    const float* wC = (const float*)d_in[6];
    const float* gN = (const float*)d_in[7];
    const float* bN = (const float*)d_in[8];
    const float* gE = (const float*)d_in[9];
    const float* bE = (const float*)d_in[10];
    float* out = (float*)d_out;

    cudaFuncSetAttribute(k_edge_mma, cudaFuncAttributeMaxDynamicSharedMemorySize, SMEM_SZ);

    k_prep<<<512, 256>>>(wC);
    k_node_gemm<<<dim3(NROWS/16, 4), 128>>>(h, wA, wB, wU, wV);
    k_edge_mma<<<EROWS/128, 256, SMEM_SZ>>>(e);
    k_node_act<<<32, 256>>>();
    k_stats<<<1, 128>>>(gE, bE, gN, bN);
    k_hout<<<NROWS*DD/256, 256>>>(h, out);
    k_eout<<<(EROWS*DD/4)/256, 256>>>(e, out + NROWS*DD);
}

// round 8
// speedup vs baseline: 1.6860x; 1.2618x over previous
#include <cuda_runtime.h>
#include <cuda_bf16.h>
#include <stdint.h>
#include <math.h>

#define BB 4
#define NN 256
#define DD 128
#define NROWS (BB*NN)            // 1024
#define EROWS (BB*NN*NN)         // 262144
#define EPSF 1e-5f

// ---------------- scratch (static device globals; no runtime allocation) ----
__device__ float g_Ah[NROWS*DD];
__device__ float g_Bh[NROWS*DD];
__device__ float g_Uh[NROWS*DD];
__device__ float g_Vh[NROWS*DD];
__device__ __nv_bfloat16 g_WB[2][DD][DD];      // wC as bf16 [hi|lo]; B(n,k)=wC[n][k]
__device__ float g_gi[(size_t)EROWS*DD];       // gate_input scratch, 134 MB
__device__ float g_agg[NROWS*DD];
__device__ float g_hact[NROWS*DD];
__device__ float g_esum[DD];
__device__ float g_esq[DD];
__device__ float g_nsum[DD];
__device__ float g_nsq[DD];
__device__ float g_par[4*DD];   // [escale | eshift | nscale | nshift]

// SMEM layout for k_edge (dynamic):
// B: 2 segs x [128 n][136 bf16]  pitch 272 B, seg 34816 B          @ 0
// A: 2 segs x [128 r][ 72 bf16]  pitch 144 B (one 64-K half), seg 18432 @ 69632
#define PITCHB  272
#define BSEG    34816
#define PITCHA  144
#define ASEG    18432
#define OFF_B   0
#define OFF_A   69632
#define OFF_AH  106496
#define OFF_RED 107008
#define SMEM_SZ 108544

// ---------------- K0a: zero accumulators ------------------------------------
__global__ void k_prep0() {
    int idx = blockIdx.x * blockDim.x + threadIdx.x;
    if (idx < NROWS*DD) g_agg[idx] = 0.f;
    if (idx < DD) {
        g_esum[idx] = 0.f; g_esq[idx] = 0.f;
        g_nsum[idx] = 0.f; g_nsq[idx] = 0.f;
    }
}
// ---------------- K0b: build bf16 hi/lo W ------------------------------------
__global__ void k_prepW(const float* __restrict__ wC) {
    int idx = blockIdx.x * blockDim.x + threadIdx.x;
    if (idx < DD*DD) {
        int n = idx >> 7, k = idx & 127;
        float x = wC[idx];
        __nv_bfloat16 hi = __float2bfloat16(x);
        __nv_bfloat16 lo = __float2bfloat16(x - __bfloat162float(hi));
        g_WB[0][n][k] = hi;
        g_WB[1][n][k] = lo;
    }
}

// ---------------- K1: Ah/Bh/Uh/Vh = h @ W^T ---------------------------------
__global__ __launch_bounds__(128) void k_node_gemm(
    const float* __restrict__ h,
    const float* __restrict__ wA, const float* __restrict__ wB,
    const float* __restrict__ wU, const float* __restrict__ wV)
{
    __shared__ float sH[16*DD];
    const float* W; float* out;
    switch (blockIdx.y) {
        case 0:  W = wA; out = g_Ah; break;
        case 1:  W = wB; out = g_Bh; break;
        case 2:  W = wU; out = g_Uh; break;
        default: W = wV; out = g_Vh; break;
    }
    const int r0 = blockIdx.x * 16;
    const int t  = threadIdx.x;
    for (int idx = t; idx < 16*DD; idx += 128) sH[idx] = h[r0*DD + idx];
    __syncthreads();

    float acc[16];
    #pragma unroll
    for (int r = 0; r < 16; r++) acc[r] = 0.f;

    const float4* Wr  = (const float4*)(W + t*DD);
    const float4* sH4 = (const float4*)sH;
    #pragma unroll 8
    for (int kq = 0; kq < 32; kq++) {
        float4 w = Wr[kq];
        #pragma unroll
        for (int r = 0; r < 16; r++) {
            float4 hv = sH4[r*32 + kq];
            acc[r] += w.x*hv.x + w.y*hv.y + w.z*hv.z + w.w*hv.w;
        }
    }
    #pragma unroll
    for (int r = 0; r < 16; r++) out[(r0 + r)*DD + t] = acc[r];
}

// ---------------- K2: HMMA edge pass (ldmatrix + 2 CTA/SM) -------------------
__global__ __launch_bounds__(256, 2) void k_edge_mma(const float* __restrict__ e)
{
    extern __shared__ char smem[];
    const uint32_t sb = (uint32_t)__cvta_generic_to_shared(smem);
    const int t = threadIdx.x;
    const int w = t >> 5, l = t & 31;
    const int g = l >> 2, tq = l & 3;
    const int r0 = blockIdx.x * 128;
    const int b  = r0 >> 16;
    const int rm = r0 & 65535;
    const int i  = rm >> 8;
    const int j0 = rm & 255;

    float* red = (float*)(smem + OFF_RED);
    if (t < DD) {
        ((float*)(smem + OFF_AH))[t] = g_Ah[(b*NN + i)*DD + t];
        red[t] = 0.f; red[DD + t] = 0.f; red[2*DD + t] = 0.f;
    }

    // --- stage B: copy g_WB (both segs, resident all kernel) ----------------
    {
        const uint4* src = (const uint4*)g_WB;   // [2][128][16] uint4
        #pragma unroll
        for (int q = 0; q < 16; q++) {
            int idx = t + q*256;                 // 0..4095
            int seg = idx >> 11;
            int rem = idx & 2047;
            int r = rem >> 4, c = rem & 15;
            *(uint4*)(smem + OFF_B + seg*BSEG + r*PITCHB + c*16) = src[idx];
        }
    }

    const int wr = w & 3;      // row quarter
    const int wc = w >> 2;     // col half
    float acc[2][8][4];
    #pragma unroll
    for (int mt = 0; mt < 2; mt++)
        #pragma unroll
        for (int nt = 0; nt < 8; nt++)
            #pragma unroll
            for (int q = 0; q < 4; q++) acc[mt][nt][q] = 0.f;

    // ldmatrix per-lane base addresses
    const uint32_t aBase = sb + OFF_A + (uint32_t)((l & 15)*PITCHA + ((l >> 4) & 1)*16);
    const uint32_t bBase = sb + OFF_B +
        (uint32_t)(((l & 7) + ((l >> 4) & 1)*8)*PITCHB + ((l >> 3) & 1)*16);

    const float4* e4 = (const float4*)e;

    for (int kh = 0; kh < 2; kh++) {
        __syncthreads();   // protect A buffer from previous iteration's readers
        // --- stage A half: 128 rows x 64 k, fp32 -> bf16 hi/lo --------------
        {
            char* sA = smem + OFF_A;
            #pragma unroll
            for (int q = 0; q < 8; q++) {
                int idx = t + q*256;             // 0..2047
                int r = idx >> 4, c = idx & 15;
                float4 v = e4[(size_t)(r0 + r)*32 + kh*16 + c];
                __nv_bfloat162 h0, h1, l0, l1;
                h0.x = __float2bfloat16(v.x); h0.y = __float2bfloat16(v.y);
                h1.x = __float2bfloat16(v.z); h1.y = __float2bfloat16(v.w);
                l0.x = __float2bfloat16(v.x - __bfloat162float(h0.x));
                l0.y = __float2bfloat16(v.y - __bfloat162float(h0.y));
                l1.x = __float2bfloat16(v.z - __bfloat162float(h1.x));
                l1.y = __float2bfloat16(v.w - __bfloat162float(h1.y));
                uint32_t off = (uint32_t)(r*PITCHA + c*8);
                *(uint2*)(sA + off)        = make_uint2(*(uint32_t*)&h0, *(uint32_t*)&h1);
                *(uint2*)(sA + ASEG + off) = make_uint2(*(uint32_t*)&l0, *(uint32_t*)&l1);
            }
        }
        __syncthreads();

        // --- MMA mainloop over this K half ----------------------------------
        #pragma unroll
        for (int sgi = 0; sgi < 3; sgi++) {
            const uint32_t pA = aBase + ((sgi == 2) ? ASEG : 0);
            const uint32_t pB = bBase + ((sgi == 1) ? BSEG : 0) + (uint32_t)(kh*128);
            #pragma unroll
            for (int ks = 0; ks < 4; ks++) {
                uint32_t a[2][4];
                #pragma unroll
                for (int mt = 0; mt < 2; mt++) {
                    uint32_t addr = pA + (uint32_t)((wr*32 + mt*16)*PITCHA + ks*32);
                    asm volatile(
                        "ldmatrix.sync.aligned.m8n8.x4.shared.b16 {%0,%1,%2,%3}, [%4];"
                        : "=r"(a[mt][0]), "=r"(a[mt][1]), "=r"(a[mt][2]), "=r"(a[mt][3])
                        : "r"(addr));
                }
                #pragma unroll
                for (int p = 0; p < 4; p++) {
                    uint32_t bq[4];
                    uint32_t addr = pB + (uint32_t)((wc*64 + p*16)*PITCHB + ks*32);
                    asm volatile(
                        "ldmatrix.sync.aligned.m8n8.x4.shared.b16 {%0,%1,%2,%3}, [%4];"
                        : "=r"(bq[0]), "=r"(bq[1]), "=r"(bq[2]), "=r"(bq[3])
                        : "r"(addr));
                    #pragma unroll
                    for (int u = 0; u < 2; u++) {
                        const int nt = p*2 + u;
                        #pragma unroll
                        for (int mt = 0; mt < 2; mt++) {
                            asm volatile(
                                "mma.sync.aligned.m16n8k16.row.col.f32.bf16.bf16.f32 "
                                "{%0,%1,%2,%3}, {%4,%5,%6,%7}, {%8,%9}, {%0,%1,%2,%3};"
                                : "+f"(acc[mt][nt][0]), "+f"(acc[mt][nt][1]),
                                  "+f"(acc[mt][nt][2]), "+f"(acc[mt][nt][3])
                                : "r"(a[mt][0]), "r"(a[mt][1]), "r"(a[mt][2]), "r"(a[mt][3]),
                                  "r"(bq[u*2]), "r"(bq[u*2+1]));
                        }
                    }
                }
            }
        }
    }

    // --- epilogue -----------------------------------------------------------
    const float* ah = (const float*)(smem + OFF_AH);
    #pragma unroll
    for (int nt = 0; nt < 8; nt++) {
        const int C = wc*64 + nt*8 + 2*tq;
        const float ah0 = ah[C], ah1 = ah[C+1];
        float s1 = 0.f, s2 = 0.f, sv = 0.f;
        float u1 = 0.f, u2 = 0.f, uv = 0.f;
        #pragma unroll
        for (int mt = 0; mt < 2; mt++) {
            #pragma unroll
            for (int hf = 0; hf < 2; hf++) {
                const int rloc = wr*32 + mt*16 + g + hf*8;
                const size_t nb = (size_t)(b*NN + j0 + rloc)*DD + C;
                float2 bh = *(const float2*)&g_Bh[nb];
                float2 vh = *(const float2*)&g_Vh[nb];
                float gi0 = acc[mt][nt][hf*2+0] + ah0 + bh.x;
                float gi1 = acc[mt][nt][hf*2+1] + ah1 + bh.y;
                *(float2*)&g_gi[(size_t)(r0 + rloc)*DD + C] = make_float2(gi0, gi1);
                s1 += gi0; s2 += gi0*gi0; sv += vh.x / (1.0f + __expf(-gi0));
                u1 += gi1; u2 += gi1*gi1; uv += vh.y / (1.0f + __expf(-gi1));
            }
        }
        #pragma unroll
        for (int m = 16; m >= 4; m >>= 1) {
            s1 += __shfl_xor_sync(0xFFFFFFFFu, s1, m);
            s2 += __shfl_xor_sync(0xFFFFFFFFu, s2, m);
            sv += __shfl_xor_sync(0xFFFFFFFFu, sv, m);
            u1 += __shfl_xor_sync(0xFFFFFFFFu, u1, m);
            u2 += __shfl_xor_sync(0xFFFFFFFFu, u2, m);
            uv += __shfl_xor_sync(0xFFFFFFFFu, uv, m);
        }
        if (g == 0) {
            atomicAdd(&red[C],            s1);
            atomicAdd(&red[C + 1],        u1);
            atomicAdd(&red[DD + C],       s2);
            atomicAdd(&red[DD + C + 1],   u2);
            atomicAdd(&red[2*DD + C],     sv);
            atomicAdd(&red[2*DD + C + 1], uv);
        }
    }
    __syncthreads();
    if (t < DD) {
        atomicAdd(&g_esum[t], red[t]);
        atomicAdd(&g_esq[t],  red[DD + t]);
        atomicAdd(&g_agg[(b*NN + i)*DD + t], red[2*DD + t]);
    }
}

// ---------------- K3: h_act = relu(Uh + agg) + node BN stats ----------------
__global__ __launch_bounds__(256) void k_node_act() {
    __shared__ float sSum[2*DD], sSq[2*DD];
    const int t = threadIdx.x;
    const int c = t & (DD - 1);
    const int half = t >> 7;
    const int r0 = blockIdx.x * 8;
    float psum = 0.f, psq = 0.f;
    for (int r = half; r < 8; r += 2) {
        int idx = (r0 + r)*DD + c;
        float v = fmaxf(g_Uh[idx] + g_agg[idx], 0.f);
        g_hact[idx] = v;
        psum += v; psq += v*v;
    }
    sSum[t] = psum; sSq[t] = psq;
    __syncthreads();
    if (t < DD) {
        atomicAdd(&g_nsum[t], sSum[t] + sSum[t + DD]);
        atomicAdd(&g_nsq[t],  sSq[t]  + sSq[t + DD]);
    }
}

// ---------------- K4: finalize BN scale/shift --------------------------------
__global__ void k_stats(const float* __restrict__ gE, const float* __restrict__ bE,
                        const float* __restrict__ gN, const float* __restrict__ bN) {
    int c = threadIdx.x;
    if (c >= DD) return;
    const float cntE = (float)EROWS, cntN = (float)NROWS;
    float em = g_esum[c] / cntE;
    float ev = g_esq[c] / cntE - em*em;
    float ei = rsqrtf(ev + EPSF);
    float esc = ei * gE[c];
    g_par[c]      = esc;
    g_par[DD + c] = bE[c] - em*esc;

    float nm = g_nsum[c] / cntN;
    float nv = g_nsq[c] / cntN - nm*nm;
    float ni = rsqrtf(nv + EPSF);
    float nsc = ni * gN[c];
    g_par[2*DD + c] = nsc;
    g_par[3*DD + c] = bN[c] - nm*nsc;
}

// ---------------- K5: h_new --------------------------------------------------
__global__ void k_hout(const float* __restrict__ h, float* __restrict__ out) {
    int idx = blockIdx.x * blockDim.x + threadIdx.x;
    if (idx >= NROWS*DD) return;
    int c = idx & (DD - 1);
    out[idx] = g_hact[idx] * g_par[2*DD + c] + g_par[3*DD + c] + h[idx];
}

// ---------------- K6: e_new (streaming, float4) ------------------------------
__global__ void k_eout(const float* __restrict__ e, float* __restrict__ out) {
    size_t i = (size_t)blockIdx.x * blockDim.x + threadIdx.x;
    const size_t total4 = (size_t)EROWS * DD / 4;
    if (i >= total4) return;
    const float4* gi4 = (const float4*)g_gi;
    const float4* e4  = (const float4*)e;
    const float4* sc4 = (const float4*)g_par;
    const float4* sh4 = (const float4*)(g_par + DD);
    int cq = (int)(i & 31);
    float4 s  = sc4[cq];
    float4 sh = sh4[cq];
    float4 g  = gi4[i];
    float4 ev = e4[i];
    float4 r;
    r.x = fmaxf(g.x*s.x + sh.x, 0.f) + ev.x;
    r.y = fmaxf(g.y*s.y + sh.y, 0.f) + ev.y;
    r.z = fmaxf(g.z*s.z + sh.z, 0.f) + ev.z;
    r.w = fmaxf(g.w*s.w + sh.w, 0.f) + ev.w;
    ((float4*)out)[i] = r;
}

// ---------------- launch -----------------------------------------------------
extern "C" void kernel_launch(void* const* d_in, const int* in_sizes, int n_in,
                              void* d_out, int out_size) {
    const float* h  = (const float*)d_in[0];
    const float* e  = (const float*)d_in[1];
    const float* wA = (const float*)d_in[2];
    const float* wB = (const float*)d_in[3];
    const float* wU = (const float*)d_in[4];
    const float* wV = (const float*)d_in[5];
    const float* wC = (const float*)d_in[6];
    const float* gN = (const float*)d_in[7];
    const float* bN = (const float*)d_in[8];
    const float* gE = (const float*)d_in[9];
    const float* bE = (const float*)d_in[10];
    float* out = (float*)d_out;

    cudaFuncSetAttribute(k_edge_mma, cudaFuncAttributeMaxDynamicSharedMemorySize, SMEM_SZ);

    k_prep0<<<512, 256>>>();                                // launch 0
    k_prepW<<<64, 256>>>(wC);                               // launch 1
    k_node_gemm<<<dim3(NROWS/16, 4), 128>>>(h, wA, wB, wU, wV);  // launch 2
    k_edge_mma<<<EROWS/128, 256, SMEM_SZ>>>(e);             // launch 3 (profiled slot)
    k_node_act<<<128, 256>>>();                             // launch 4
    k_stats<<<1, 128>>>(gE, bE, gN, bN);                    // launch 5
    k_hout<<<NROWS*DD/256, 256>>>(h, out);                  // launch 6
    k_eout<<<(EROWS*DD/4)/256, 256>>>(e, out + NROWS*DD);   // launch 7
}

// round 10
// speedup vs baseline: 1.8141x; 1.0760x over previous
#include <cuda_runtime.h>
#include <cuda_bf16.h>
#include <stdint.h>
#include <math.h>

#define BB 4
#define NN 256
#define DD 128
#define NROWS (BB*NN)            // 1024
#define EROWS (BB*NN*NN)         // 262144
#define EPSF 1e-5f

// ---------------- scratch (static device globals; no runtime allocation) ----
__device__ float g_Ah[NROWS*DD];
__device__ float g_Bh[NROWS*DD];
__device__ float g_Uh[NROWS*DD];
__device__ float g_Vh[NROWS*DD];
__device__ __nv_bfloat16 g_WB[2][DD][DD];      // wC as bf16 [hi|lo]; B(n,k)=wC[n][k]
__device__ float g_gi[(size_t)EROWS*DD];       // gate_input scratch, 134 MB
__device__ float g_agg[NROWS*DD];
__device__ float g_hact[NROWS*DD];
__device__ float g_esum[DD];
__device__ float g_esq[DD];
__device__ float g_nsum[DD];
__device__ float g_nsq[DD];
__device__ float g_par[4*DD];   // [escale | eshift | nscale | nshift]

// SMEM layout for k_edge (dynamic):
// B: 2 segs x [128 n][136 bf16]  pitch 272 B, seg 34816 B          @ 0
// A: 2 segs x [128 r][ 72 bf16]  pitch 144 B (one 64-K half), seg 18432 @ 69632
// After MMA: fp32 acc tile 128 x 132 (67584 B) aliases [0, 67584)
#define PITCHB  272
#define BSEG    34816
#define PITCHA  144
#define ASEG    18432
#define OFF_B   0
#define OFF_A   69632
#define OFF_AH  106496
#define OFF_RED 107008
#define SMEM_SZ 108544
#define CPITCH  132

// ---------------- K0a: zero accumulators ------------------------------------
__global__ void k_prep0() {
    int idx = blockIdx.x * blockDim.x + threadIdx.x;
    if (idx < NROWS*DD) g_agg[idx] = 0.f;
    if (idx < DD) {
        g_esum[idx] = 0.f; g_esq[idx] = 0.f;
        g_nsum[idx] = 0.f; g_nsq[idx] = 0.f;
    }
}
// ---------------- K0b: build bf16 hi/lo W ------------------------------------
__global__ void k_prepW(const float* __restrict__ wC) {
    int idx = blockIdx.x * blockDim.x + threadIdx.x;
    if (idx < DD*DD) {
        int n = idx >> 7, k = idx & 127;
        float x = wC[idx];
        __nv_bfloat16 hi = __float2bfloat16(x);
        __nv_bfloat16 lo = __float2bfloat16(x - __bfloat162float(hi));
        g_WB[0][n][k] = hi;
        g_WB[1][n][k] = lo;
    }
}

// ---------------- K1: Ah/Bh/Uh/Vh = h @ W^T ---------------------------------
__global__ __launch_bounds__(128) void k_node_gemm(
    const float* __restrict__ h,
    const float* __restrict__ wA, const float* __restrict__ wB,
    const float* __restrict__ wU, const float* __restrict__ wV)
{
    __shared__ float sH[16*DD];
    const float* W; float* out;
    switch (blockIdx.y) {
        case 0:  W = wA; out = g_Ah; break;
        case 1:  W = wB; out = g_Bh; break;
        case 2:  W = wU; out = g_Uh; break;
        default: W = wV; out = g_Vh; break;
    }
    const int r0 = blockIdx.x * 16;
    const int t  = threadIdx.x;
    for (int idx = t; idx < 16*DD; idx += 128) sH[idx] = h[r0*DD + idx];
    __syncthreads();

    float acc[16];
    #pragma unroll
    for (int r = 0; r < 16; r++) acc[r] = 0.f;

    const float4* Wr  = (const float4*)(W + t*DD);
    const float4* sH4 = (const float4*)sH;
    #pragma unroll 8
    for (int kq = 0; kq < 32; kq++) {
        float4 w = Wr[kq];
        #pragma unroll
        for (int r = 0; r < 16; r++) {
            float4 hv = sH4[r*32 + kq];
            acc[r] += w.x*hv.x + w.y*hv.y + w.z*hv.z + w.w*hv.w;
        }
    }
    #pragma unroll
    for (int r = 0; r < 16; r++) out[(r0 + r)*DD + t] = acc[r];
}

// ---------------- K2: HMMA edge pass (ldmatrix + coalesced epilogue) ---------
__global__ __launch_bounds__(256, 2) void k_edge_mma(const float* __restrict__ e)
{
    extern __shared__ char smem[];
    const uint32_t sb = (uint32_t)__cvta_generic_to_shared(smem);
    const int t = threadIdx.x;
    const int w = t >> 5, l = t & 31;
    const int g = l >> 2, tq = l & 3;
    const int r0 = blockIdx.x * 128;
    const int b  = r0 >> 16;
    const int rm = r0 & 65535;
    const int i  = rm >> 8;
    const int j0 = rm & 255;

    float* red = (float*)(smem + OFF_RED);
    if (t < DD) {
        ((float*)(smem + OFF_AH))[t] = g_Ah[(b*NN + i)*DD + t];
        red[t] = 0.f; red[DD + t] = 0.f; red[2*DD + t] = 0.f;
    }

    // --- stage B: copy g_WB (both segs, resident through MMA) ---------------
    {
        const uint4* src = (const uint4*)g_WB;   // [2][128][16] uint4
        #pragma unroll
        for (int q = 0; q < 16; q++) {
            int idx = t + q*256;                 // 0..4095
            int seg = idx >> 11;
            int rem = idx & 2047;
            int r = rem >> 4, c = rem & 15;
            *(uint4*)(smem + OFF_B + seg*BSEG + r*PITCHB + c*16) = src[idx];
        }
    }

    const int wr = w & 3;      // row quarter
    const int wc = w >> 2;     // col half
    float acc[2][8][4];
    #pragma unroll
    for (int mt = 0; mt < 2; mt++)
        #pragma unroll
        for (int nt = 0; nt < 8; nt++)
            #pragma unroll
            for (int q = 0; q < 4; q++) acc[mt][nt][q] = 0.f;

    const uint32_t aBase = sb + OFF_A + (uint32_t)((l & 15)*PITCHA + ((l >> 4) & 1)*16);
    const uint32_t bBase = sb + OFF_B +
        (uint32_t)(((l & 7) + ((l >> 4) & 1)*8)*PITCHB + ((l >> 3) & 1)*16);

    const float4* e4 = (const float4*)e;

    for (int kh = 0; kh < 2; kh++) {
        __syncthreads();
        // --- stage A half: 128 rows x 64 k, fp32 -> bf16 hi/lo --------------
        {
            char* sA = smem + OFF_A;
            #pragma unroll
            for (int q = 0; q < 8; q++) {
                int idx = t + q*256;             // 0..2047
                int r = idx >> 4, c = idx & 15;
                float4 v = e4[(size_t)(r0 + r)*32 + kh*16 + c];
                __nv_bfloat162 h0, h1, l0, l1;
                h0.x = __float2bfloat16(v.x); h0.y = __float2bfloat16(v.y);
                h1.x = __float2bfloat16(v.z); h1.y = __float2bfloat16(v.w);
                l0.x = __float2bfloat16(v.x - __bfloat162float(h0.x));
                l0.y = __float2bfloat16(v.y - __bfloat162float(h0.y));
                l1.x = __float2bfloat16(v.z - __bfloat162float(h1.x));
                l1.y = __float2bfloat16(v.w - __bfloat162float(h1.y));
                uint32_t off = (uint32_t)(r*PITCHA + c*8);
                *(uint2*)(sA + off)        = make_uint2(*(uint32_t*)&h0, *(uint32_t*)&h1);
                *(uint2*)(sA + ASEG + off) = make_uint2(*(uint32_t*)&l0, *(uint32_t*)&l1);
            }
        }
        __syncthreads();

        // --- MMA mainloop over this K half ----------------------------------
        #pragma unroll
        for (int sgi = 0; sgi < 3; sgi++) {
            const uint32_t pA = aBase + ((sgi == 2) ? ASEG : 0);
            const uint32_t pB = bBase + ((sgi == 1) ? BSEG : 0) + (uint32_t)(kh*128);
            #pragma unroll
            for (int ks = 0; ks < 4; ks++) {
                uint32_t a[2][4];
                #pragma unroll
                for (int mt = 0; mt < 2; mt++) {
                    uint32_t addr = pA + (uint32_t)((wr*32 + mt*16)*PITCHA + ks*32);
                    asm volatile(
                        "ldmatrix.sync.aligned.m8n8.x4.shared.b16 {%0,%1,%2,%3}, [%4];"
                        : "=r"(a[mt][0]), "=r"(a[mt][1]), "=r"(a[mt][2]), "=r"(a[mt][3])
                        : "r"(addr));
                }
                #pragma unroll
                for (int p = 0; p < 4; p++) {
                    uint32_t bq[4];
                    uint32_t addr = pB + (uint32_t)((wc*64 + p*16)*PITCHB + ks*32);
                    asm volatile(
                        "ldmatrix.sync.aligned.m8n8.x4.shared.b16 {%0,%1,%2,%3}, [%4];"
                        : "=r"(bq[0]), "=r"(bq[1]), "=r"(bq[2]), "=r"(bq[3])
                        : "r"(addr));
                    #pragma unroll
                    for (int u = 0; u < 2; u++) {
                        const int nt = p*2 + u;
                        #pragma unroll
                        for (int mt = 0; mt < 2; mt++) {
                            asm volatile(
                                "mma.sync.aligned.m16n8k16.row.col.f32.bf16.bf16.f32 "
                                "{%0,%1,%2,%3}, {%4,%5,%6,%7}, {%8,%9}, {%0,%1,%2,%3};"
                                : "+f"(acc[mt][nt][0]), "+f"(acc[mt][nt][1]),
                                  "+f"(acc[mt][nt][2]), "+f"(acc[mt][nt][3])
                                : "r"(a[mt][0]), "r"(a[mt][1]), "r"(a[mt][2]), "r"(a[mt][3]),
                                  "r"(bq[u*2]), "r"(bq[u*2+1]));
                        }
                    }
                }
            }
        }
    }
    __syncthreads();     // all warps done reading A/B smem

    // --- epilogue phase 1: accumulators -> fp32 smem tile (pitch 132) -------
    {
        float* sc = (float*)smem;
        #pragma unroll
        for (int mt = 0; mt < 2; mt++)
            #pragma unroll
            for (int nt = 0; nt < 8; nt++)
                #pragma unroll
                for (int hf = 0; hf < 2; hf++) {
                    int rloc = wr*32 + mt*16 + g + hf*8;
                    int C = wc*64 + nt*8 + 2*tq;
                    *(float2*)&sc[rloc*CPITCH + C] =
                        make_float2(acc[mt][nt][hf*2], acc[mt][nt][hf*2+1]);
                }
    }
    __syncthreads();

    // --- epilogue phase 2: coalesced column pass ----------------------------
    {
        const float* sc = (const float*)smem;
        const float* ah = (const float*)(smem + OFF_AH);
        const int c2 = (t & 63)*2;
        const int rq = t >> 6;
        const float ah0 = ah[c2], ah1 = ah[c2+1];
        const float* BhB = g_Bh + (size_t)(b*NN + j0 + rq*32)*DD + c2;
        const float* VhB = g_Vh + (size_t)(b*NN + j0 + rq*32)*DD + c2;
        float*       giB = g_gi + (size_t)(r0 + rq*32)*DD + c2;
        float s1 = 0.f, s2 = 0.f, sv = 0.f;
        float u1 = 0.f, u2 = 0.f, uv = 0.f;
        #pragma unroll 4
        for (int ri = 0; ri < 32; ri++) {
            int r = rq*32 + ri;
            float2 a2 = *(const float2*)&sc[r*CPITCH + c2];
            float2 bh = *(const float2*)(BhB + (size_t)ri*DD);
            float2 vh = *(const float2*)(VhB + (size_t)ri*DD);
            float gi0 = a2.x + ah0 + bh.x;
            float gi1 = a2.y + ah1 + bh.y;
            *(float2*)(giB + (size_t)ri*DD) = make_float2(gi0, gi1);
            s1 += gi0; s2 += gi0*gi0; sv += vh.x / (1.0f + __expf(-gi0));
            u1 += gi1; u2 += gi1*gi1; uv += vh.y / (1.0f + __expf(-gi1));
        }
        atomicAdd(&red[c2],          s1);
        atomicAdd(&red[c2 + 1],      u1);
        atomicAdd(&red[DD + c2],     s2);
        atomicAdd(&red[DD + c2 + 1], u2);
        atomicAdd(&red[2*DD + c2],       sv);
        atomicAdd(&red[2*DD + c2 + 1],   uv);
    }
    __syncthreads();
    if (t < DD) {
        atomicAdd(&g_esum[t], red[t]);
        atomicAdd(&g_esq[t],  red[DD + t]);
        atomicAdd(&g_agg[(b*NN + i)*DD + t], red[2*DD + t]);
    }
}

// ---------------- K3: h_act = relu(Uh + agg) + node BN stats ----------------
__global__ __launch_bounds__(256) void k_node_act() {
    __shared__ float sSum[2*DD], sSq[2*DD];
    const int t = threadIdx.x;
    const int c = t & (DD - 1);
    const int half = t >> 7;
    const int r0 = blockIdx.x * 8;
    float psum = 0.f, psq = 0.f;
    for (int r = half; r < 8; r += 2) {
        int idx = (r0 + r)*DD + c;
        float v = fmaxf(g_Uh[idx] + g_agg[idx], 0.f);
        g_hact[idx] = v;
        psum += v; psq += v*v;
    }
    sSum[t] = psum; sSq[t] = psq;
    __syncthreads();
    if (t < DD) {
        atomicAdd(&g_nsum[t], sSum[t] + sSum[t + DD]);
        atomicAdd(&g_nsq[t],  sSq[t]  + sSq[t + DD]);
    }
}

// ---------------- K4: finalize BN scale/shift --------------------------------
__global__ void k_stats(const float* __restrict__ gE, const float* __restrict__ bE,
                        const float* __restrict__ gN, const float* __restrict__ bN) {
    int c = threadIdx.x;
    if (c >= DD) return;
    const float cntE = (float)EROWS, cntN = (float)NROWS;
    float em = g_esum[c] / cntE;
    float ev = g_esq[c] / cntE - em*em;
    float ei = rsqrtf(ev + EPSF);
    float esc = ei * gE[c];
    g_par[c]      = esc;
    g_par[DD + c] = bE[c] - em*esc;

    float nm = g_nsum[c] / cntN;
    float nv = g_nsq[c] / cntN - nm*nm;
    float ni = rsqrtf(nv + EPSF);
    float nsc = ni * gN[c];
    g_par[2*DD + c] = nsc;
    g_par[3*DD + c] = bN[c] - nm*nsc;
}

// ---------------- K5: h_new --------------------------------------------------
__global__ void k_hout(const float* __restrict__ h, float* __restrict__ out) {
    int idx = blockIdx.x * blockDim.x + threadIdx.x;
    if (idx >= NROWS*DD) return;
    int c = idx & (DD - 1);
    out[idx] = g_hact[idx] * g_par[2*DD + c] + g_par[3*DD + c] + h[idx];
}

// ---------------- K6: e_new (streaming, float4) ------------------------------
__global__ void k_eout(const float* __restrict__ e, float* __restrict__ out) {
    size_t i = (size_t)blockIdx.x * blockDim.x + threadIdx.x;
    const size_t total4 = (size_t)EROWS * DD / 4;
    if (i >= total4) return;
    const float4* gi4 = (const float4*)g_gi;
    const float4* e4  = (const float4*)e;
    const float4* sc4 = (const float4*)g_par;
    const float4* sh4 = (const float4*)(g_par + DD);
    int cq = (int)(i & 31);
    float4 s  = sc4[cq];
    float4 sh = sh4[cq];
    float4 g  = gi4[i];
    float4 ev = e4[i];
    float4 r;
    r.x = fmaxf(g.x*s.x + sh.x, 0.f) + ev.x;
    r.y = fmaxf(g.y*s.y + sh.y, 0.f) + ev.y;
    r.z = fmaxf(g.z*s.z + sh.z, 0.f) + ev.z;
    r.w = fmaxf(g.w*s.w + sh.w, 0.f) + ev.w;
    ((float4*)out)[i] = r;
}

// ---------------- launch -----------------------------------------------------
extern "C" void kernel_launch(void* const* d_in, const int* in_sizes, int n_in,
                              void* d_out, int out_size) {
    const float* h  = (const float*)d_in[0];
    const float* e  = (const float*)d_in[1];
    const float* wA = (const float*)d_in[2];
    const float* wB = (const float*)d_in[3];
    const float* wU = (const float*)d_in[4];
    const float* wV = (const float*)d_in[5];
    const float* wC = (const float*)d_in[6];
    const float* gN = (const float*)d_in[7];
    const float* bN = (const float*)d_in[8];
    const float* gE = (const float*)d_in[9];
    const float* bE = (const float*)d_in[10];
    float* out = (float*)d_out;

    cudaFuncSetAttribute(k_edge_mma, cudaFuncAttributeMaxDynamicSharedMemorySize, SMEM_SZ);

    k_prep0<<<512, 256>>>();                                // launch 0
    k_prepW<<<64, 256>>>(wC);                               // launch 1
    k_node_gemm<<<dim3(NROWS/16, 4), 128>>>(h, wA, wB, wU, wV);  // launch 2
    k_edge_mma<<<EROWS/128, 256, SMEM_SZ>>>(e);             // launch 3 (profiled slot)
    k_node_act<<<128, 256>>>();                             // launch 4
    k_stats<<<1, 128>>>(gE, bE, gN, bN);                    // launch 5
    k_hout<<<NROWS*DD/256, 256>>>(h, out);                  // launch 6
    k_eout<<<(EROWS*DD/4)/256, 256>>>(e, out + NROWS*DD);   // launch 7
}

// round 11
// speedup vs baseline: 2.1047x; 1.1602x over previous
#include <cuda_runtime.h>
#include <cuda_bf16.h>
#include <cuda_fp16.h>
#include <stdint.h>
#include <math.h>

#define BB 4
#define NN 256
#define DD 128
#define NROWS (BB*NN)            // 1024
#define EROWS (BB*NN*NN)         // 262144
#define EPSF 1e-5f

// ---------------- scratch (static device globals; no runtime allocation) ----
__device__ float g_Ah[NROWS*DD];
__device__ float g_Bh[NROWS*DD];
__device__ float g_Uh[NROWS*DD];
__device__ float g_Vh[NROWS*DD];
__device__ __nv_bfloat16 g_WB[2][DD][DD];      // wC as bf16 [hi|lo]; B(n,k)=wC[n][k]
__device__ __half g_gih[(size_t)EROWS*DD];     // gate_input scratch, fp16, 67 MB
__device__ float g_agg[NROWS*DD];
__device__ float g_hact[NROWS*DD];
__device__ float g_esum[DD];
__device__ float g_esq[DD];
__device__ float g_nsum[DD];
__device__ float g_nsq[DD];
__device__ float g_par[4*DD];   // [escale | eshift | nscale | nshift]

// SMEM layout for k_edge (dynamic):
// B: 2 segs x [128 n][136 bf16]  pitch 272 B, seg 34816 B          @ 0
// A: 2 segs x [128 r][ 72 bf16]  pitch 144 B (one 64-K half), seg 18432 @ 69632
// After MMA: fp32 acc tile 128 x 132 (67584 B) aliases [0, 67584)
#define PITCHB  272
#define BSEG    34816
#define PITCHA  144
#define ASEG    18432
#define OFF_B   0
#define OFF_A   69632
#define OFF_AH  106496
#define OFF_RED 107008
#define SMEM_SZ 108544
#define CPITCH  132

// ---------------- K0a: zero accumulators ------------------------------------
__global__ void k_prep0() {
    int idx = blockIdx.x * blockDim.x + threadIdx.x;
    if (idx < NROWS*DD) g_agg[idx] = 0.f;
    if (idx < DD) {
        g_esum[idx] = 0.f; g_esq[idx] = 0.f;
        g_nsum[idx] = 0.f; g_nsq[idx] = 0.f;
    }
}
// ---------------- K0b: build bf16 hi/lo W ------------------------------------
__global__ void k_prepW(const float* __restrict__ wC) {
    int idx = blockIdx.x * blockDim.x + threadIdx.x;
    if (idx < DD*DD) {
        int n = idx >> 7, k = idx & 127;
        float x = wC[idx];
        __nv_bfloat16 hi = __float2bfloat16(x);
        __nv_bfloat16 lo = __float2bfloat16(x - __bfloat162float(hi));
        g_WB[0][n][k] = hi;
        g_WB[1][n][k] = lo;
    }
}

// ---------------- K1: Ah/Bh/Uh/Vh = h @ W^T ---------------------------------
__global__ __launch_bounds__(128) void k_node_gemm(
    const float* __restrict__ h,
    const float* __restrict__ wA, const float* __restrict__ wB,
    const float* __restrict__ wU, const float* __restrict__ wV)
{
    __shared__ float sH[16*DD];
    const float* W; float* out;
    switch (blockIdx.y) {
        case 0:  W = wA; out = g_Ah; break;
        case 1:  W = wB; out = g_Bh; break;
        case 2:  W = wU; out = g_Uh; break;
        default: W = wV; out = g_Vh; break;
    }
    const int r0 = blockIdx.x * 16;
    const int t  = threadIdx.x;
    for (int idx = t; idx < 16*DD; idx += 128) sH[idx] = h[r0*DD + idx];
    __syncthreads();

    float acc[16];
    #pragma unroll
    for (int r = 0; r < 16; r++) acc[r] = 0.f;

    const float4* Wr  = (const float4*)(W + t*DD);
    const float4* sH4 = (const float4*)sH;
    #pragma unroll 8
    for (int kq = 0; kq < 32; kq++) {
        float4 w = Wr[kq];
        #pragma unroll
        for (int r = 0; r < 16; r++) {
            float4 hv = sH4[r*32 + kq];
            acc[r] += w.x*hv.x + w.y*hv.y + w.z*hv.z + w.w*hv.w;
        }
    }
    #pragma unroll
    for (int r = 0; r < 16; r++) out[(r0 + r)*DD + t] = acc[r];
}

// ---------------- K2: HMMA edge pass (hoisted ldmatrix, fp16 gi out) ---------
__global__ __launch_bounds__(256, 2) void k_edge_mma(const float* __restrict__ e)
{
    extern __shared__ char smem[];
    const uint32_t sb = (uint32_t)__cvta_generic_to_shared(smem);
    const int t = threadIdx.x;
    const int w = t >> 5, l = t & 31;
    const int g = l >> 2, tq = l & 3;
    const int r0 = blockIdx.x * 128;
    const int b  = r0 >> 16;
    const int rm = r0 & 65535;
    const int i  = rm >> 8;
    const int j0 = rm & 255;

    float* red = (float*)(smem + OFF_RED);
    if (t < DD) {
        ((float*)(smem + OFF_AH))[t] = g_Ah[(b*NN + i)*DD + t];
        red[t] = 0.f; red[DD + t] = 0.f; red[2*DD + t] = 0.f;
    }

    // --- stage B: copy g_WB (both segs, resident through MMA) ---------------
    {
        const uint4* src = (const uint4*)g_WB;   // [2][128][16] uint4
        #pragma unroll
        for (int q = 0; q < 16; q++) {
            int idx = t + q*256;                 // 0..4095
            int seg = idx >> 11;
            int rem = idx & 2047;
            int r = rem >> 4, c = rem & 15;
            *(uint4*)(smem + OFF_B + seg*BSEG + r*PITCHB + c*16) = src[idx];
        }
    }

    const int wr = w & 3;      // row quarter
    const int wc = w >> 2;     // col half
    float acc[2][8][4];
    #pragma unroll
    for (int mt = 0; mt < 2; mt++)
        #pragma unroll
        for (int nt = 0; nt < 8; nt++)
            #pragma unroll
            for (int q = 0; q < 4; q++) acc[mt][nt][q] = 0.f;

    const uint32_t aBase = sb + OFF_A + (uint32_t)((l & 15)*PITCHA + ((l >> 4) & 1)*16);
    const uint32_t bBase = sb + OFF_B +
        (uint32_t)(((l & 7) + ((l >> 4) & 1)*8)*PITCHB + ((l >> 3) & 1)*16);

    const float4* e4 = (const float4*)e;

    for (int kh = 0; kh < 2; kh++) {
        __syncthreads();
        // --- stage A half: 128 rows x 64 k, fp32 -> bf16 hi/lo --------------
        {
            char* sA = smem + OFF_A;
            #pragma unroll
            for (int q = 0; q < 8; q++) {
                int idx = t + q*256;             // 0..2047
                int r = idx >> 4, c = idx & 15;
                float4 v = e4[(size_t)(r0 + r)*32 + kh*16 + c];
                __nv_bfloat162 h0, h1, l0, l1;
                h0.x = __float2bfloat16(v.x); h0.y = __float2bfloat16(v.y);
                h1.x = __float2bfloat16(v.z); h1.y = __float2bfloat16(v.w);
                l0.x = __float2bfloat16(v.x - __bfloat162float(h0.x));
                l0.y = __float2bfloat16(v.y - __bfloat162float(h0.y));
                l1.x = __float2bfloat16(v.z - __bfloat162float(h1.x));
                l1.y = __float2bfloat16(v.w - __bfloat162float(h1.y));
                uint32_t off = (uint32_t)(r*PITCHA + c*8);
                *(uint2*)(sA + off)        = make_uint2(*(uint32_t*)&h0, *(uint32_t*)&h1);
                *(uint2*)(sA + ASEG + off) = make_uint2(*(uint32_t*)&l0, *(uint32_t*)&l1);
            }
        }
        __syncthreads();

        // --- MMA mainloop: fragments loaded once, reused across 3 products --
        const uint32_t pAhi = aBase;
        const uint32_t pAlo = aBase + ASEG;
        const uint32_t pBhi = bBase + (uint32_t)(kh*128);
        const uint32_t pBlo = bBase + BSEG + (uint32_t)(kh*128);
        #pragma unroll
        for (int ks = 0; ks < 4; ks++) {
            uint32_t ah[2][4], al[2][4];
            #pragma unroll
            for (int mt = 0; mt < 2; mt++) {
                const uint32_t roff = (uint32_t)((wr*32 + mt*16)*PITCHA + ks*32);
                asm volatile(
                    "ldmatrix.sync.aligned.m8n8.x4.shared.b16 {%0,%1,%2,%3}, [%4];"
                    : "=r"(ah[mt][0]), "=r"(ah[mt][1]), "=r"(ah[mt][2]), "=r"(ah[mt][3])
                    : "r"(pAhi + roff));
                asm volatile(
                    "ldmatrix.sync.aligned.m8n8.x4.shared.b16 {%0,%1,%2,%3}, [%4];"
                    : "=r"(al[mt][0]), "=r"(al[mt][1]), "=r"(al[mt][2]), "=r"(al[mt][3])
                    : "r"(pAlo + roff));
            }
            #pragma unroll
            for (int p = 0; p < 4; p++) {
                const uint32_t boff = (uint32_t)((wc*64 + p*16)*PITCHB + ks*32);
                uint32_t bh[4], bl[4];
                asm volatile(
                    "ldmatrix.sync.aligned.m8n8.x4.shared.b16 {%0,%1,%2,%3}, [%4];"
                    : "=r"(bh[0]), "=r"(bh[1]), "=r"(bh[2]), "=r"(bh[3])
                    : "r"(pBhi + boff));
                asm volatile(
                    "ldmatrix.sync.aligned.m8n8.x4.shared.b16 {%0,%1,%2,%3}, [%4];"
                    : "=r"(bl[0]), "=r"(bl[1]), "=r"(bl[2]), "=r"(bl[3])
                    : "r"(pBlo + boff));
                #pragma unroll
                for (int sgi = 0; sgi < 3; sgi++) {
                    const uint32_t (*aa)[4] = (sgi == 2) ? al : ah;
                    const uint32_t* bb      = (sgi == 1) ? bl : bh;
                    #pragma unroll
                    for (int u = 0; u < 2; u++) {
                        const int nt = p*2 + u;
                        #pragma unroll
                        for (int mt = 0; mt < 2; mt++) {
                            asm volatile(
                                "mma.sync.aligned.m16n8k16.row.col.f32.bf16.bf16.f32 "
                                "{%0,%1,%2,%3}, {%4,%5,%6,%7}, {%8,%9}, {%0,%1,%2,%3};"
                                : "+f"(acc[mt][nt][0]), "+f"(acc[mt][nt][1]),
                                  "+f"(acc[mt][nt][2]), "+f"(acc[mt][nt][3])
                                : "r"(aa[mt][0]), "r"(aa[mt][1]), "r"(aa[mt][2]), "r"(aa[mt][3]),
                                  "r"(bb[u*2]), "r"(bb[u*2+1]));
                        }
                    }
                }
            }
        }
    }
    __syncthreads();     // all warps done reading A/B smem

    // --- epilogue phase 1: accumulators -> fp32 smem tile (pitch 132) -------
    {
        float* sc = (float*)smem;
        #pragma unroll
        for (int mt = 0; mt < 2; mt++)
            #pragma unroll
            for (int nt = 0; nt < 8; nt++)
                #pragma unroll
                for (int hf = 0; hf < 2; hf++) {
                    int rloc = wr*32 + mt*16 + g + hf*8;
                    int C = wc*64 + nt*8 + 2*tq;
                    *(float2*)&sc[rloc*CPITCH + C] =
                        make_float2(acc[mt][nt][hf*2], acc[mt][nt][hf*2+1]);
                }
    }
    __syncthreads();

    // --- epilogue phase 2: coalesced column pass ----------------------------
    {
        const float* sc = (const float*)smem;
        const float* ah = (const float*)(smem + OFF_AH);
        const int c2 = (t & 63)*2;
        const int rq = t >> 6;
        const float ah0 = ah[c2], ah1 = ah[c2+1];
        const float* BhB = g_Bh + (size_t)(b*NN + j0 + rq*32)*DD + c2;
        const float* VhB = g_Vh + (size_t)(b*NN + j0 + rq*32)*DD + c2;
        __half*      giB = g_gih + (size_t)(r0 + rq*32)*DD + c2;
        float s1 = 0.f, s2 = 0.f, sv = 0.f;
        float u1 = 0.f, u2 = 0.f, uv = 0.f;
        #pragma unroll 4
        for (int ri = 0; ri < 32; ri++) {
            int r = rq*32 + ri;
            float2 a2 = *(const float2*)&sc[r*CPITCH + c2];
            float2 bh = *(const float2*)(BhB + (size_t)ri*DD);
            float2 vh = *(const float2*)(VhB + (size_t)ri*DD);
            float gi0 = a2.x + ah0 + bh.x;
            float gi1 = a2.y + ah1 + bh.y;
            *(__half2*)(giB + (size_t)ri*DD) = __floats2half2_rn(gi0, gi1);
            s1 += gi0; s2 += gi0*gi0; sv += vh.x / (1.0f + __expf(-gi0));
            u1 += gi1; u2 += gi1*gi1; uv += vh.y / (1.0f + __expf(-gi1));
        }
        atomicAdd(&red[c2],          s1);
        atomicAdd(&red[c2 + 1],      u1);
        atomicAdd(&red[DD + c2],     s2);
        atomicAdd(&red[DD + c2 + 1], u2);
        atomicAdd(&red[2*DD + c2],       sv);
        atomicAdd(&red[2*DD + c2 + 1],   uv);
    }
    __syncthreads();
    if (t < DD) {
        atomicAdd(&g_esum[t], red[t]);
        atomicAdd(&g_esq[t],  red[DD + t]);
        atomicAdd(&g_agg[(b*NN + i)*DD + t], red[2*DD + t]);
    }
}

// ---------------- K3: h_act = relu(Uh + agg) + node BN stats ----------------
__global__ __launch_bounds__(256) void k_node_act() {
    __shared__ float sSum[2*DD], sSq[2*DD];
    const int t = threadIdx.x;
    const int c = t & (DD - 1);
    const int half = t >> 7;
    const int r0 = blockIdx.x * 8;
    float psum = 0.f, psq = 0.f;
    for (int r = half; r < 8; r += 2) {
        int idx = (r0 + r)*DD + c;
        float v = fmaxf(g_Uh[idx] + g_agg[idx], 0.f);
        g_hact[idx] = v;
        psum += v; psq += v*v;
    }
    sSum[t] = psum; sSq[t] = psq;
    __syncthreads();
    if (t < DD) {
        atomicAdd(&g_nsum[t], sSum[t] + sSum[t + DD]);
        atomicAdd(&g_nsq[t],  sSq[t]  + sSq[t + DD]);
    }
}

// ---------------- K4: finalize BN scale/shift --------------------------------
__global__ void k_stats(const float* __restrict__ gE, const float* __restrict__ bE,
                        const float* __restrict__ gN, const float* __restrict__ bN) {
    int c = threadIdx.x;
    if (c >= DD) return;
    const float cntE = (float)EROWS, cntN = (float)NROWS;
    float em = g_esum[c] / cntE;
    float ev = g_esq[c] / cntE - em*em;
    float ei = rsqrtf(ev + EPSF);
    float esc = ei * gE[c];
    g_par[c]      = esc;
    g_par[DD + c] = bE[c] - em*esc;

    float nm = g_nsum[c] / cntN;
    float nv = g_nsq[c] / cntN - nm*nm;
    float ni = rsqrtf(nv + EPSF);
    float nsc = ni * gN[c];
    g_par[2*DD + c] = nsc;
    g_par[3*DD + c] = bN[c] - nm*nsc;
}

// ---------------- K5: h_new --------------------------------------------------
__global__ void k_hout(const float* __restrict__ h, float* __restrict__ out) {
    int idx = blockIdx.x * blockDim.x + threadIdx.x;
    if (idx >= NROWS*DD) return;
    int c = idx & (DD - 1);
    out[idx] = g_hact[idx] * g_par[2*DD + c] + g_par[3*DD + c] + h[idx];
}

// ---------------- K6: e_new (streaming; fp16 gi in, float4 out) --------------
__global__ void k_eout(const float* __restrict__ e, float* __restrict__ out) {
    size_t i = (size_t)blockIdx.x * blockDim.x + threadIdx.x;
    const size_t total4 = (size_t)EROWS * DD / 4;
    if (i >= total4) return;
    const uint2* gi2  = (const uint2*)g_gih;       // 4 halves per uint2
    const float4* e4  = (const float4*)e;
    const float4* sc4 = (const float4*)g_par;
    const float4* sh4 = (const float4*)(g_par + DD);
    int cq = (int)(i & 31);
    float4 s  = sc4[cq];
    float4 sh = sh4[cq];
    uint2 gp  = gi2[i];
    float2 g0 = __half22float2(*(const __half2*)&gp.x);
    float2 g1 = __half22float2(*(const __half2*)&gp.y);
    float4 ev = e4[i];
    float4 r;
    r.x = fmaxf(g0.x*s.x + sh.x, 0.f) + ev.x;
    r.y = fmaxf(g0.y*s.y + sh.y, 0.f) + ev.y;
    r.z = fmaxf(g1.x*s.z + sh.z, 0.f) + ev.z;
    r.w = fmaxf(g1.y*s.w + sh.w, 0.f) + ev.w;
    ((float4*)out)[i] = r;
}

// ---------------- launch -----------------------------------------------------
extern "C" void kernel_launch(void* const* d_in, const int* in_sizes, int n_in,
                              void* d_out, int out_size) {
    const float* h  = (const float*)d_in[0];
    const float* e  = (const float*)d_in[1];
    const float* wA = (const float*)d_in[2];
    const float* wB = (const float*)d_in[3];
    const float* wU = (const float*)d_in[4];
    const float* wV = (const float*)d_in[5];
    const float* wC = (const float*)d_in[6];
    const float* gN = (const float*)d_in[7];
    const float* bN = (const float*)d_in[8];
    const float* gE = (const float*)d_in[9];
    const float* bE = (const float*)d_in[10];
    float* out = (float*)d_out;

    cudaFuncSetAttribute(k_edge_mma, cudaFuncAttributeMaxDynamicSharedMemorySize, SMEM_SZ);

    k_prep0<<<512, 256>>>();                                // launch 0
    k_prepW<<<64, 256>>>(wC);                               // launch 1
    k_node_gemm<<<dim3(NROWS/16, 4), 128>>>(h, wA, wB, wU, wV);  // launch 2
    k_edge_mma<<<EROWS/128, 256, SMEM_SZ>>>(e);             // launch 3 (profiled slot)
    k_node_act<<<128, 256>>>();                             // launch 4
    k_stats<<<1, 128>>>(gE, bE, gN, bN);                    // launch 5
    k_hout<<<NROWS*DD/256, 256>>>(h, out);                  // launch 6
    k_eout<<<(EROWS*DD/4)/256, 256>>>(e, out + NROWS*DD);   // launch 7
}

// round 14
// speedup vs baseline: 2.5148x; 1.1949x over previous
#include <cuda_runtime.h>
#include <cuda_bf16.h>
#include <cuda_fp16.h>
#include <stdint.h>
#include <math.h>

#define BB 4
#define NN 256
#define DD 128
#define NROWS (BB*NN)            // 1024
#define EROWS (BB*NN*NN)         // 262144
#define EPSF 1e-5f

// ---------------- scratch (static device globals; no runtime allocation) ----
__device__ float g_Ah[NROWS*DD];
__device__ float g_Bh[NROWS*DD];
__device__ float g_Uh[NROWS*DD];
__device__ float g_Vh[NROWS*DD];
__device__ __nv_bfloat16 g_WB[2][DD][DD];      // wC as bf16 [hi|lo]; B(n,k)=wC[n][k]
__device__ __half g_gih[(size_t)EROWS*DD];     // gate_input scratch, fp16, 67 MB
__device__ float g_agg[NROWS*DD];
__device__ float g_hact[NROWS*DD];
__device__ float g_esum[DD];
__device__ float g_esq[DD];
__device__ float g_nsum[DD];
__device__ float g_nsq[DD];
__device__ float g_par[4*DD];   // [escale | eshift | nscale | nshift]

// SMEM layout for k_edge (dynamic):
// B: 2 segs x [128 n][136 bf16]  pitch 272 B, seg 34816 B          @ 0
// A: 2 segs x [128 r][ 72 bf16]  pitch 144 B (one 64-K half), seg 18432 @ 69632
// After MMA: fp32 acc tile 128 x 132 (67584 B) aliases [0, 67584)
#define PITCHB  272
#define BSEG    34816
#define PITCHA  144
#define ASEG    18432
#define OFF_B   0
#define OFF_A   69632
#define OFF_AH  106496
#define OFF_RED 107008
#define SMEM_SZ 108544
#define CPITCH  132

__device__ __forceinline__ float sigmoid_fast(float x) {
    float t;
    asm("tanh.approx.f32 %0, %1;" : "=f"(t) : "f"(x * 0.5f));
    return fmaf(t, 0.5f, 0.5f);
}

// ---------------- K0a: zero accumulators ------------------------------------
__global__ void k_prep0() {
    int idx = blockIdx.x * blockDim.x + threadIdx.x;
    if (idx < NROWS*DD) g_agg[idx] = 0.f;
    if (idx < DD) {
        g_esum[idx] = 0.f; g_esq[idx] = 0.f;
        g_nsum[idx] = 0.f; g_nsq[idx] = 0.f;
    }
}
// ---------------- K0b: build bf16 hi/lo W ------------------------------------
__global__ void k_prepW(const float* __restrict__ wC) {
    int idx = blockIdx.x * blockDim.x + threadIdx.x;
    if (idx < DD*DD) {
        int n = idx >> 7, k = idx & 127;
        float x = wC[idx];
        __nv_bfloat16 hi = __float2bfloat16(x);
        __nv_bfloat16 lo = __float2bfloat16(x - __bfloat162float(hi));
        g_WB[0][n][k] = hi;
        g_WB[1][n][k] = lo;
    }
}

// ---------------- K1: Ah/Bh/Uh/Vh = h @ W^T ---------------------------------
__global__ __launch_bounds__(128) void k_node_gemm(
    const float* __restrict__ h,
    const float* __restrict__ wA, const float* __restrict__ wB,
    const float* __restrict__ wU, const float* __restrict__ wV)
{
    __shared__ float sH[16*DD];
    const float* W; float* out;
    switch (blockIdx.y) {
        case 0:  W = wA; out = g_Ah; break;
        case 1:  W = wB; out = g_Bh; break;
        case 2:  W = wU; out = g_Uh; break;
        default: W = wV; out = g_Vh; break;
    }
    const int r0 = blockIdx.x * 16;
    const int t  = threadIdx.x;
    for (int idx = t; idx < 16*DD; idx += 128) sH[idx] = h[r0*DD + idx];
    __syncthreads();

    float acc[16];
    #pragma unroll
    for (int r = 0; r < 16; r++) acc[r] = 0.f;

    const float4* Wr  = (const float4*)(W + t*DD);
    const float4* sH4 = (const float4*)sH;
    #pragma unroll 8
    for (int kq = 0; kq < 32; kq++) {
        float4 w = Wr[kq];
        #pragma unroll
        for (int r = 0; r < 16; r++) {
            float4 hv = sH4[r*32 + kq];
            acc[r] += w.x*hv.x + w.y*hv.y + w.z*hv.z + w.w*hv.w;
        }
    }
    #pragma unroll
    for (int r = 0; r < 16; r++) out[(r0 + r)*DD + t] = acc[r];
}

// ---------------- K2: HMMA edge pass ----------------------------------------
__global__ __launch_bounds__(256, 2) void k_edge_mma(const float* __restrict__ e)
{
    extern __shared__ char smem[];
    const uint32_t sb = (uint32_t)__cvta_generic_to_shared(smem);
    const int t = threadIdx.x;
    const int w = t >> 5, l = t & 31;
    const int g = l >> 2, tq = l & 3;
    const int r0 = blockIdx.x * 128;
    const int b  = r0 >> 16;
    const int rm = r0 & 65535;
    const int i  = rm >> 8;
    const int j0 = rm & 255;

    float* red = (float*)(smem + OFF_RED);
    if (t < DD) {
        ((float*)(smem + OFF_AH))[t] = g_Ah[(b*NN + i)*DD + t];
        red[t] = 0.f; red[DD + t] = 0.f; red[2*DD + t] = 0.f;
    }

    // --- stage B: copy g_WB (both segs, resident through MMA) ---------------
    {
        const uint4* src = (const uint4*)g_WB;   // [2][128][16] uint4
        #pragma unroll
        for (int q = 0; q < 16; q++) {
            int idx = t + q*256;                 // 0..4095
            int seg = idx >> 11;
            int rem = idx & 2047;
            int r = rem >> 4, c = rem & 15;
            *(uint4*)(smem + OFF_B + seg*BSEG + r*PITCHB + c*16) = src[idx];
        }
    }

    const int wr = w & 3;      // row quarter
    const int wc = w >> 2;     // col half
    float acc[2][8][4];
    #pragma unroll
    for (int mt = 0; mt < 2; mt++)
        #pragma unroll
        for (int nt = 0; nt < 8; nt++)
            #pragma unroll
            for (int q = 0; q < 4; q++) acc[mt][nt][q] = 0.f;

    const uint32_t aBase = sb + OFF_A + (uint32_t)((l & 15)*PITCHA + ((l >> 4) & 1)*16);
    const uint32_t bBase = sb + OFF_B +
        (uint32_t)(((l & 7) + ((l >> 4) & 1)*8)*PITCHB + ((l >> 3) & 1)*16);

    const float4* e4 = (const float4*)e;

    for (int kh = 0; kh < 2; kh++) {
        __syncthreads();
        // --- stage A half: 128 rows x 64 k, fp32 -> bf16 hi/lo (packed cvt) -
        {
            char* sA = smem + OFF_A;
            #pragma unroll
            for (int q = 0; q < 8; q++) {
                int idx = t + q*256;             // 0..2047
                int r = idx >> 4, c = idx & 15;
                float4 v = e4[(size_t)(r0 + r)*32 + kh*16 + c];
                __nv_bfloat162 hp0 = __floats2bfloat162_rn(v.x, v.y);
                __nv_bfloat162 hp1 = __floats2bfloat162_rn(v.z, v.w);
                float2 hf0 = __bfloat1622float2(hp0);
                float2 hf1 = __bfloat1622float2(hp1);
                __nv_bfloat162 lp0 = __floats2bfloat162_rn(v.x - hf0.x, v.y - hf0.y);
                __nv_bfloat162 lp1 = __floats2bfloat162_rn(v.z - hf1.x, v.w - hf1.y);
                uint32_t off = (uint32_t)(r*PITCHA + c*8);
                *(uint2*)(sA + off)        = make_uint2(*(uint32_t*)&hp0, *(uint32_t*)&hp1);
                *(uint2*)(sA + ASEG + off) = make_uint2(*(uint32_t*)&lp0, *(uint32_t*)&lp1);
            }
        }
        __syncthreads();

        // --- MMA mainloop: fragments loaded once, reused across 3 products --
        const uint32_t pAhi = aBase;
        const uint32_t pAlo = aBase + ASEG;
        const uint32_t pBhi = bBase + (uint32_t)(kh*128);
        const uint32_t pBlo = bBase + BSEG + (uint32_t)(kh*128);
        #pragma unroll
        for (int ks = 0; ks < 4; ks++) {
            uint32_t ah[2][4], al[2][4];
            #pragma unroll
            for (int mt = 0; mt < 2; mt++) {
                const uint32_t roff = (uint32_t)((wr*32 + mt*16)*PITCHA + ks*32);
                asm volatile(
                    "ldmatrix.sync.aligned.m8n8.x4.shared.b16 {%0,%1,%2,%3}, [%4];"
                    : "=r"(ah[mt][0]), "=r"(ah[mt][1]), "=r"(ah[mt][2]), "=r"(ah[mt][3])
                    : "r"(pAhi + roff));
                asm volatile(
                    "ldmatrix.sync.aligned.m8n8.x4.shared.b16 {%0,%1,%2,%3}, [%4];"
                    : "=r"(al[mt][0]), "=r"(al[mt][1]), "=r"(al[mt][2]), "=r"(al[mt][3])
                    : "r"(pAlo + roff));
            }
            #pragma unroll
            for (int p = 0; p < 4; p++) {
                const uint32_t boff = (uint32_t)((wc*64 + p*16)*PITCHB + ks*32);
                uint32_t bh[4], bl[4];
                asm volatile(
                    "ldmatrix.sync.aligned.m8n8.x4.shared.b16 {%0,%1,%2,%3}, [%4];"
                    : "=r"(bh[0]), "=r"(bh[1]), "=r"(bh[2]), "=r"(bh[3])
                    : "r"(pBhi + boff));
                asm volatile(
                    "ldmatrix.sync.aligned.m8n8.x4.shared.b16 {%0,%1,%2,%3}, [%4];"
                    : "=r"(bl[0]), "=r"(bl[1]), "=r"(bl[2]), "=r"(bl[3])
                    : "r"(pBlo + boff));
                #pragma unroll
                for (int sgi = 0; sgi < 3; sgi++) {
                    const uint32_t (*aa)[4] = (sgi == 2) ? al : ah;
                    const uint32_t* bb      = (sgi == 1) ? bl : bh;
                    #pragma unroll
                    for (int u = 0; u < 2; u++) {
                        const int nt = p*2 + u;
                        #pragma unroll
                        for (int mt = 0; mt < 2; mt++) {
                            asm volatile(
                                "mma.sync.aligned.m16n8k16.row.col.f32.bf16.bf16.f32 "
                                "{%0,%1,%2,%3}, {%4,%5,%6,%7}, {%8,%9}, {%0,%1,%2,%3};"
                                : "+f"(acc[mt][nt][0]), "+f"(acc[mt][nt][1]),
                                  "+f"(acc[mt][nt][2]), "+f"(acc[mt][nt][3])
                                : "r"(aa[mt][0]), "r"(aa[mt][1]), "r"(aa[mt][2]), "r"(aa[mt][3]),
                                  "r"(bb[u*2]), "r"(bb[u*2+1]));
                        }
                    }
                }
            }
        }
    }
    __syncthreads();     // all warps done reading A/B smem

    // --- epilogue phase 1: accumulators -> fp32 smem tile (pitch 132) -------
    {
        float* sc = (float*)smem;
        #pragma unroll
        for (int mt = 0; mt < 2; mt++)
            #pragma unroll
            for (int nt = 0; nt < 8; nt++)
                #pragma unroll
                for (int hf = 0; hf < 2; hf++) {
                    int rloc = wr*32 + mt*16 + g + hf*8;
                    int C = wc*64 + nt*8 + 2*tq;
                    *(float2*)&sc[rloc*CPITCH + C] =
                        make_float2(acc[mt][nt][hf*2], acc[mt][nt][hf*2+1]);
                }
    }
    __syncthreads();

    // --- epilogue phase 2: 128-bit coalesced column pass --------------------
    // warp w: rows w*16..w*16+15; lane l: cols 4l..4l+3
    {
        const float* sc = (const float*)smem;
        const float4 ah4 = *(const float4*)((const float*)(smem + OFF_AH) + 4*l);
        const int c4 = 4*l;
        const float* BhB = g_Bh + (size_t)(b*NN + j0 + w*16)*DD + c4;
        const float* VhB = g_Vh + (size_t)(b*NN + j0 + w*16)*DD + c4;
        __half*      giB = g_gih + (size_t)(r0 + w*16)*DD + c4;
        float4 s1 = make_float4(0.f,0.f,0.f,0.f);
        float4 s2 = make_float4(0.f,0.f,0.f,0.f);
        float4 sv = make_float4(0.f,0.f,0.f,0.f);
        #pragma unroll 4
        for (int ri = 0; ri < 16; ri++) {
            int r = w*16 + ri;
            float4 a4 = *(const float4*)&sc[r*CPITCH + c4];
            float4 bh = *(const float4*)(BhB + (size_t)ri*DD);
            float4 vh = *(const float4*)(VhB + (size_t)ri*DD);
            float4 gi;
            gi.x = a4.x + ah4.x + bh.x;
            gi.y = a4.y + ah4.y + bh.y;
            gi.z = a4.z + ah4.z + bh.z;
            gi.w = a4.w + ah4.w + bh.w;
            __half2 h01 = __floats2half2_rn(gi.x, gi.y);
            __half2 h23 = __floats2half2_rn(gi.z, gi.w);
            *(uint2*)(giB + (size_t)ri*DD) =
                make_uint2(*(uint32_t*)&h01, *(uint32_t*)&h23);
            s1.x += gi.x; s1.y += gi.y; s1.z += gi.z; s1.w += gi.w;
            s2.x += gi.x*gi.x; s2.y += gi.y*gi.y; s2.z += gi.z*gi.z; s2.w += gi.w*gi.w;
            sv.x += vh.x * sigmoid_fast(gi.x);
            sv.y += vh.y * sigmoid_fast(gi.y);
            sv.z += vh.z * sigmoid_fast(gi.z);
            sv.w += vh.w * sigmoid_fast(gi.w);
        }
        atomicAdd(&red[c4+0], s1.x); atomicAdd(&red[c4+1], s1.y);
        atomicAdd(&red[c4+2], s1.z); atomicAdd(&red[c4+3], s1.w);
        atomicAdd(&red[DD+c4+0], s2.x); atomicAdd(&red[DD+c4+1], s2.y);
        atomicAdd(&red[DD+c4+2], s2.z); atomicAdd(&red[DD+c4+3], s2.w);
        atomicAdd(&red[2*DD+c4+0], sv.x); atomicAdd(&red[2*DD+c4+1], sv.y);
        atomicAdd(&red[2*DD+c4+2], sv.z); atomicAdd(&red[2*DD+c4+3], sv.w);
    }
    __syncthreads();
    if (t < DD) {
        atomicAdd(&g_esum[t], red[t]);
        atomicAdd(&g_esq[t],  red[DD + t]);
        atomicAdd(&g_agg[(b*NN + i)*DD + t], red[2*DD + t]);
    }
}

// ---------------- K3: h_act = relu(Uh + agg) + node BN stats ----------------
__global__ __launch_bounds__(256) void k_node_act() {
    __shared__ float sSum[2*DD], sSq[2*DD];
    const int t = threadIdx.x;
    const int c = t & (DD - 1);
    const int half = t >> 7;
    const int r0 = blockIdx.x * 8;
    float psum = 0.f, psq = 0.f;
    for (int r = half; r < 8; r += 2) {
        int idx = (r0 + r)*DD + c;
        float v = fmaxf(g_Uh[idx] + g_agg[idx], 0.f);
        g_hact[idx] = v;
        psum += v; psq += v*v;
    }
    sSum[t] = psum; sSq[t] = psq;
    __syncthreads();
    if (t < DD) {
        atomicAdd(&g_nsum[t], sSum[t] + sSum[t + DD]);
        atomicAdd(&g_nsq[t],  sSq[t]  + sSq[t + DD]);
    }
}

// ---------------- K4: finalize BN scale/shift --------------------------------
__global__ void k_stats(const float* __restrict__ gE, const float* __restrict__ bE,
                        const float* __restrict__ gN, const float* __restrict__ bN) {
    int c = threadIdx.x;
    if (c >= DD) return;
    const float cntE = (float)EROWS, cntN = (float)NROWS;
    float em = g_esum[c] / cntE;
    float ev = g_esq[c] / cntE - em*em;
    float ei = rsqrtf(ev + EPSF);
    float esc = ei * gE[c];
    g_par[c]      = esc;
    g_par[DD + c] = bE[c] - em*esc;

    float nm = g_nsum[c] / cntN;
    float nv = g_nsq[c] / cntN - nm*nm;
    float ni = rsqrtf(nv + EPSF);
    float nsc = ni * gN[c];
    g_par[2*DD + c] = nsc;
    g_par[3*DD + c] = bN[c] - nm*nsc;
}

// ---------------- K5: h_new --------------------------------------------------
__global__ void k_hout(const float* __restrict__ h, float* __restrict__ out) {
    int idx = blockIdx.x * blockDim.x + threadIdx.x;
    if (idx >= NROWS*DD) return;
    int c = idx & (DD - 1);
    out[idx] = g_hact[idx] * g_par[2*DD + c] + g_par[3*DD + c] + h[idx];
}

// ---------------- K6: e_new (streaming; fp16 gi in, float4 out) --------------
__global__ void k_eout(const float* __restrict__ e, float* __restrict__ out) {
    size_t i = (size_t)blockIdx.x * blockDim.x + threadIdx.x;
    const size_t total4 = (size_t)EROWS * DD / 4;
    if (i >= total4) return;
    const uint2* gi2  = (const uint2*)g_gih;       // 4 halves per uint2
    const float4* e4  = (const float4*)e;
    const float4* sc4 = (const float4*)g_par;
    const float4* sh4 = (const float4*)(g_par + DD);
    int cq = (int)(i & 31);
    float4 s  = sc4[cq];
    float4 sh = sh4[cq];
    uint2 gp  = gi2[i];
    float2 g0 = __half22float2(*(const __half2*)&gp.x);
    float2 g1 = __half22float2(*(const __half2*)&gp.y);
    float4 ev = e4[i];
    float4 r;
    r.x = fmaxf(g0.x*s.x + sh.x, 0.f) + ev.x;
    r.y = fmaxf(g0.y*s.y + sh.y, 0.f) + ev.y;
    r.z = fmaxf(g1.x*s.z + sh.z, 0.f) + ev.z;
    r.w = fmaxf(g1.y*s.w + sh.w, 0.f) + ev.w;
    ((float4*)out)[i] = r;
}

// ---------------- launch -----------------------------------------------------
extern "C" void kernel_launch(void* const* d_in, const int* in_sizes, int n_in,
                              void* d_out, int out_size) {
    const float* h  = (const float*)d_in[0];
    const float* e  = (const float*)d_in[1];
    const float* wA = (const float*)d_in[2];
    const float* wB = (const float*)d_in[3];
    const float* wU = (const float*)d_in[4];
    const float* wV = (const float*)d_in[5];
    const float* wC = (const float*)d_in[6];
    const float* gN = (const float*)d_in[7];
    const float* bN = (const float*)d_in[8];
    const float* gE = (const float*)d_in[9];
    const float* bE = (const float*)d_in[10];
    float* out = (float*)d_out;

    cudaFuncSetAttribute(k_edge_mma, cudaFuncAttributeMaxDynamicSharedMemorySize, SMEM_SZ);

    k_prep0<<<512, 256>>>();                                // launch 0
    k_prepW<<<64, 256>>>(wC);                               // launch 1
    k_node_gemm<<<dim3(NROWS/16, 4), 128>>>(h, wA, wB, wU, wV);  // launch 2
    k_edge_mma<<<EROWS/128, 256, SMEM_SZ>>>(e);             // launch 3 (profiled slot)
    k_node_act<<<128, 256>>>();                             // launch 4
    k_stats<<<1, 128>>>(gE, bE, gN, bN);                    // launch 5
    k_hout<<<NROWS*DD/256, 256>>>(h, out);                  // launch 6
    k_eout<<<(EROWS*DD/4)/256, 256>>>(e, out + NROWS*DD);   // launch 7
}

// round 16
// speedup vs baseline: 2.7711x; 1.1019x over previous
#include <cuda_runtime.h>
#include <cuda_bf16.h>
#include <cuda_fp16.h>
#include <stdint.h>
#include <math.h>

#define BB 4
#define NN 256
#define DD 128
#define NROWS (BB*NN)            // 1024
#define EROWS (BB*NN*NN)         // 262144
#define EPSF 1e-5f

// ---------------- scratch (static device globals; no runtime allocation) ----
__device__ float g_Ah[NROWS*DD];
__device__ float g_Bh[NROWS*DD];
__device__ float g_Uh[NROWS*DD];
__device__ float g_Vh[NROWS*DD];
__device__ __half g_WH[DD*DD];                 // wC as fp16; B(n,k)=wC[n][k]
__device__ __half g_gih[(size_t)EROWS*DD];     // gate_input scratch, fp16, 67 MB
__device__ float g_agg[NROWS*DD];
__device__ float g_hact[NROWS*DD];
__device__ float g_esum[DD];
__device__ float g_esq[DD];
__device__ float g_nsum[DD];
__device__ float g_nsq[DD];
__device__ float g_par[4*DD];   // [escale | eshift | nscale | nshift]

// SMEM layout for k_edge (dynamic):
// B: 1 seg  [128 n][136 fp16]  pitch 272 B                     @ 0      (34816 B)
// A: 2 segs [128 r][ 72 fp16]  pitch 144 B (one 64-K half)     @ 34816  (2x18432)
// After MMA: fp32 acc tile 128 x 132 (67584 B) aliases [0, 67584)
#define PITCHB  272
#define PITCHA  144
#define ASEG    18432
#define OFF_B   0
#define OFF_A   34816
#define OFF_AH  71680
#define OFF_RED 72192
#define SMEM_SZ 73728
#define CPITCH  132

__device__ __forceinline__ float sigmoid_fast(float x) {
    float t;
    asm("tanh.approx.f32 %0, %1;" : "=f"(t) : "f"(x * 0.5f));
    return fmaf(t, 0.5f, 0.5f);
}

// ---------------- K0: zero accumulators + build fp16 W ----------------------
__global__ void k_prep(const float* __restrict__ wC) {
    int idx = blockIdx.x * blockDim.x + threadIdx.x;
    if (idx < NROWS*DD) g_agg[idx] = 0.f;
    if (idx < DD) {
        g_esum[idx] = 0.f; g_esq[idx] = 0.f;
        g_nsum[idx] = 0.f; g_nsq[idx] = 0.f;
    }
    if (idx < DD*DD) g_WH[idx] = __float2half_rn(wC[idx]);
}

// ---------------- K1: Ah/Bh/Uh/Vh = h @ W^T ---------------------------------
__global__ __launch_bounds__(128) void k_node_gemm(
    const float* __restrict__ h,
    const float* __restrict__ wA, const float* __restrict__ wB,
    const float* __restrict__ wU, const float* __restrict__ wV)
{
    __shared__ float sH[16*DD];
    const float* W; float* out;
    switch (blockIdx.y) {
        case 0:  W = wA; out = g_Ah; break;
        case 1:  W = wB; out = g_Bh; break;
        case 2:  W = wU; out = g_Uh; break;
        default: W = wV; out = g_Vh; break;
    }
    const int r0 = blockIdx.x * 16;
    const int t  = threadIdx.x;
    for (int idx = t; idx < 16*DD; idx += 128) sH[idx] = h[r0*DD + idx];
    __syncthreads();

    float acc[16];
    #pragma unroll
    for (int r = 0; r < 16; r++) acc[r] = 0.f;

    const float4* Wr  = (const float4*)(W + t*DD);
    const float4* sH4 = (const float4*)sH;
    #pragma unroll 8
    for (int kq = 0; kq < 32; kq++) {
        float4 w = Wr[kq];
        #pragma unroll
        for (int r = 0; r < 16; r++) {
            float4 hv = sH4[r*32 + kq];
            acc[r] += w.x*hv.x + w.y*hv.y + w.z*hv.z + w.w*hv.w;
        }
    }
    #pragma unroll
    for (int r = 0; r < 16; r++) out[(r0 + r)*DD + t] = acc[r];
}

// ---------------- K2: HMMA edge pass (fp16 2-product split) ------------------
__global__ __launch_bounds__(256, 2) void k_edge_mma(const float* __restrict__ e)
{
    extern __shared__ char smem[];
    const uint32_t sb = (uint32_t)__cvta_generic_to_shared(smem);
    const int t = threadIdx.x;
    const int w = t >> 5, l = t & 31;
    const int g = l >> 2, tq = l & 3;
    const int r0 = blockIdx.x * 128;
    const int b  = r0 >> 16;
    const int rm = r0 & 65535;
    const int i  = rm >> 8;
    const int j0 = rm & 255;

    float* red = (float*)(smem + OFF_RED);
    if (t < DD) {
        ((float*)(smem + OFF_AH))[t] = g_Ah[(b*NN + i)*DD + t];
        red[t] = 0.f; red[DD + t] = 0.f; red[2*DD + t] = 0.f;
    }

    // --- stage B: copy g_WH (fp16, one seg; 16 uint4 = 256 B per row) -------
    {
        const uint4* src = (const uint4*)g_WH;   // 2048 uint4, 16 per row
        #pragma unroll
        for (int q = 0; q < 8; q++) {
            int idx = t + q*256;                 // 0..2047
            int r = idx >> 4, c = idx & 15;
            *(uint4*)(smem + OFF_B + r*PITCHB + c*16) = src[idx];
        }
    }

    const int wr = w & 3;      // row quarter
    const int wc = w >> 2;     // col half
    float acc[2][8][4];
    #pragma unroll
    for (int mt = 0; mt < 2; mt++)
        #pragma unroll
        for (int nt = 0; nt < 8; nt++)
            #pragma unroll
            for (int q = 0; q < 4; q++) acc[mt][nt][q] = 0.f;

    const uint32_t aBase = sb + OFF_A + (uint32_t)((l & 15)*PITCHA + ((l >> 4) & 1)*16);
    const uint32_t bBase = sb + OFF_B +
        (uint32_t)(((l & 7) + ((l >> 4) & 1)*8)*PITCHB + ((l >> 3) & 1)*16);

    const float4* e4 = (const float4*)e;

    for (int kh = 0; kh < 2; kh++) {
        __syncthreads();
        // --- stage A half: 128 rows x 64 k, fp32 -> fp16 hi/lo --------------
        {
            char* sA = smem + OFF_A;
            #pragma unroll
            for (int q = 0; q < 8; q++) {
                int idx = t + q*256;             // 0..2047
                int r = idx >> 4, c = idx & 15;
                float4 v = e4[(size_t)(r0 + r)*32 + kh*16 + c];
                __half2 hp0 = __floats2half2_rn(v.x, v.y);
                __half2 hp1 = __floats2half2_rn(v.z, v.w);
                float2 hf0 = __half22float2(hp0);
                float2 hf1 = __half22float2(hp1);
                __half2 lp0 = __floats2half2_rn(v.x - hf0.x, v.y - hf0.y);
                __half2 lp1 = __floats2half2_rn(v.z - hf1.x, v.w - hf1.y);
                uint32_t off = (uint32_t)(r*PITCHA + c*8);
                *(uint2*)(sA + off)        = make_uint2(*(uint32_t*)&hp0, *(uint32_t*)&hp1);
                *(uint2*)(sA + ASEG + off) = make_uint2(*(uint32_t*)&lp0, *(uint32_t*)&lp1);
            }
        }
        __syncthreads();

        // --- MMA mainloop: A hi/lo x B (single fp16 W) ----------------------
        const uint32_t pAhi = aBase;
        const uint32_t pAlo = aBase + ASEG;
        const uint32_t pB   = bBase + (uint32_t)(kh*128);
        #pragma unroll
        for (int ks = 0; ks < 4; ks++) {
            uint32_t ah[2][4], al[2][4];
            #pragma unroll
            for (int mt = 0; mt < 2; mt++) {
                const uint32_t roff = (uint32_t)((wr*32 + mt*16)*PITCHA + ks*32);
                asm volatile(
                    "ldmatrix.sync.aligned.m8n8.x4.shared.b16 {%0,%1,%2,%3}, [%4];"
                    : "=r"(ah[mt][0]), "=r"(ah[mt][1]), "=r"(ah[mt][2]), "=r"(ah[mt][3])
                    : "r"(pAhi + roff));
                asm volatile(
                    "ldmatrix.sync.aligned.m8n8.x4.shared.b16 {%0,%1,%2,%3}, [%4];"
                    : "=r"(al[mt][0]), "=r"(al[mt][1]), "=r"(al[mt][2]), "=r"(al[mt][3])
                    : "r"(pAlo + roff));
            }
            #pragma unroll
            for (int p = 0; p < 4; p++) {
                uint32_t bq[4];
                const uint32_t boff = (uint32_t)((wc*64 + p*16)*PITCHB + ks*32);
                asm volatile(
                    "ldmatrix.sync.aligned.m8n8.x4.shared.b16 {%0,%1,%2,%3}, [%4];"
                    : "=r"(bq[0]), "=r"(bq[1]), "=r"(bq[2]), "=r"(bq[3])
                    : "r"(pB + boff));
                #pragma unroll
                for (int prod = 0; prod < 2; prod++) {
                    const uint32_t (*aa)[4] = prod ? al : ah;
                    #pragma unroll
                    for (int u = 0; u < 2; u++) {
                        const int nt = p*2 + u;
                        #pragma unroll
                        for (int mt = 0; mt < 2; mt++) {
                            asm volatile(
                                "mma.sync.aligned.m16n8k16.row.col.f32.f16.f16.f32 "
                                "{%0,%1,%2,%3}, {%4,%5,%6,%7}, {%8,%9}, {%0,%1,%2,%3};"
                                : "+f"(acc[mt][nt][0]), "+f"(acc[mt][nt][1]),
                                  "+f"(acc[mt][nt][2]), "+f"(acc[mt][nt][3])
                                : "r"(aa[mt][0]), "r"(aa[mt][1]), "r"(aa[mt][2]), "r"(aa[mt][3]),
                                  "r"(bq[u*2]), "r"(bq[u*2+1]));
                        }
                    }
                }
            }
        }
    }
    __syncthreads();     // all warps done reading A/B smem

    // --- epilogue phase 1: accumulators -> fp32 smem tile (pitch 132) -------
    {
        float* sc = (float*)smem;
        #pragma unroll
        for (int mt = 0; mt < 2; mt++)
            #pragma unroll
            for (int nt = 0; nt < 8; nt++)
                #pragma unroll
                for (int hf = 0; hf < 2; hf++) {
                    int rloc = wr*32 + mt*16 + g + hf*8;
                    int C = wc*64 + nt*8 + 2*tq;
                    *(float2*)&sc[rloc*CPITCH + C] =
                        make_float2(acc[mt][nt][hf*2], acc[mt][nt][hf*2+1]);
                }
    }
    __syncthreads();

    // --- epilogue phase 2: 128-bit coalesced column pass --------------------
    {
        const float* sc = (const float*)smem;
        const float4 ah4 = *(const float4*)((const float*)(smem + OFF_AH) + 4*l);
        const int c4 = 4*l;
        const float* BhB = g_Bh + (size_t)(b*NN + j0 + w*16)*DD + c4;
        const float* VhB = g_Vh + (size_t)(b*NN + j0 + w*16)*DD + c4;
        __half*      giB = g_gih + (size_t)(r0 + w*16)*DD + c4;
        float4 s1 = make_float4(0.f,0.f,0.f,0.f);
        float4 s2 = make_float4(0.f,0.f,0.f,0.f);
        float4 sv = make_float4(0.f,0.f,0.f,0.f);
        #pragma unroll 4
        for (int ri = 0; ri < 16; ri++) {
            int r = w*16 + ri;
            float4 a4 = *(const float4*)&sc[r*CPITCH + c4];
            float4 bh = *(const float4*)(BhB + (size_t)ri*DD);
            float4 vh = *(const float4*)(VhB + (size_t)ri*DD);
            float4 gi;
            gi.x = a4.x + ah4.x + bh.x;
            gi.y = a4.y + ah4.y + bh.y;
            gi.z = a4.z + ah4.z + bh.z;
            gi.w = a4.w + ah4.w + bh.w;
            __half2 h01 = __floats2half2_rn(gi.x, gi.y);
            __half2 h23 = __floats2half2_rn(gi.z, gi.w);
            *(uint2*)(giB + (size_t)ri*DD) =
                make_uint2(*(uint32_t*)&h01, *(uint32_t*)&h23);
            s1.x += gi.x; s1.y += gi.y; s1.z += gi.z; s1.w += gi.w;
            s2.x += gi.x*gi.x; s2.y += gi.y*gi.y; s2.z += gi.z*gi.z; s2.w += gi.w*gi.w;
            sv.x += vh.x * sigmoid_fast(gi.x);
            sv.y += vh.y * sigmoid_fast(gi.y);
            sv.z += vh.z * sigmoid_fast(gi.z);
            sv.w += vh.w * sigmoid_fast(gi.w);
        }
        atomicAdd(&red[c4+0], s1.x); atomicAdd(&red[c4+1], s1.y);
        atomicAdd(&red[c4+2], s1.z); atomicAdd(&red[c4+3], s1.w);
        atomicAdd(&red[DD+c4+0], s2.x); atomicAdd(&red[DD+c4+1], s2.y);
        atomicAdd(&red[DD+c4+2], s2.z); atomicAdd(&red[DD+c4+3], s2.w);
        atomicAdd(&red[2*DD+c4+0], sv.x); atomicAdd(&red[2*DD+c4+1], sv.y);
        atomicAdd(&red[2*DD+c4+2], sv.z); atomicAdd(&red[2*DD+c4+3], sv.w);
    }
    __syncthreads();
    if (t < DD) {
        atomicAdd(&g_esum[t], red[t]);
        atomicAdd(&g_esq[t],  red[DD + t]);
        atomicAdd(&g_agg[(b*NN + i)*DD + t], red[2*DD + t]);
    }
}

// ---------------- K3: h_act = relu(Uh + agg) + node BN stats ----------------
__global__ __launch_bounds__(256) void k_node_act() {
    __shared__ float sSum[2*DD], sSq[2*DD];
    const int t = threadIdx.x;
    const int c = t & (DD - 1);
    const int half = t >> 7;
    const int r0 = blockIdx.x * 8;
    float psum = 0.f, psq = 0.f;
    for (int r = half; r < 8; r += 2) {
        int idx = (r0 + r)*DD + c;
        float v = fmaxf(g_Uh[idx] + g_agg[idx], 0.f);
        g_hact[idx] = v;
        psum += v; psq += v*v;
    }
    sSum[t] = psum; sSq[t] = psq;
    __syncthreads();
    if (t < DD) {
        atomicAdd(&g_nsum[t], sSum[t] + sSum[t + DD]);
        atomicAdd(&g_nsq[t],  sSq[t]  + sSq[t + DD]);
    }
}

// ---------------- K4: finalize BN scale/shift --------------------------------
__global__ void k_stats(const float* __restrict__ gE, const float* __restrict__ bE,
                        const float* __restrict__ gN, const float* __restrict__ bN) {
    int c = threadIdx.x;
    if (c >= DD) return;
    const float cntE = (float)EROWS, cntN = (float)NROWS;
    float em = g_esum[c] / cntE;
    float ev = g_esq[c] / cntE - em*em;
    float ei = rsqrtf(ev + EPSF);
    float esc = ei * gE[c];
    g_par[c]      = esc;
    g_par[DD + c] = bE[c] - em*esc;

    float nm = g_nsum[c] / cntN;
    float nv = g_nsq[c] / cntN - nm*nm;
    float ni = rsqrtf(nv + EPSF);
    float nsc = ni * gN[c];
    g_par[2*DD + c] = nsc;
    g_par[3*DD + c] = bN[c] - nm*nsc;
}

// ---------------- K5: h_new --------------------------------------------------
__global__ void k_hout(const float* __restrict__ h, float* __restrict__ out) {
    int idx = blockIdx.x * blockDim.x + threadIdx.x;
    if (idx >= NROWS*DD) return;
    int c = idx & (DD - 1);
    out[idx] = g_hact[idx] * g_par[2*DD + c] + g_par[3*DD + c] + h[idx];
}

// ---------------- K6: e_new (streaming; fp16 gi in, float4 out) --------------
__global__ void k_eout(const float* __restrict__ e, float* __restrict__ out) {
    size_t i = (size_t)blockIdx.x * blockDim.x + threadIdx.x;
    const size_t total4 = (size_t)EROWS * DD / 4;
    if (i >= total4) return;
    const uint2* gi2  = (const uint2*)g_gih;       // 4 halves per uint2
    const float4* e4  = (const float4*)e;
    const float4* sc4 = (const float4*)g_par;
    const float4* sh4 = (const float4*)(g_par + DD);
    int cq = (int)(i & 31);
    float4 s  = sc4[cq];
    float4 sh = sh4[cq];
    uint2 gp  = gi2[i];
    float2 g0 = __half22float2(*(const __half2*)&gp.x);
    float2 g1 = __half22float2(*(const __half2*)&gp.y);
    float4 ev = e4[i];
    float4 r;
    r.x = fmaxf(g0.x*s.x + sh.x, 0.f) + ev.x;
    r.y = fmaxf(g0.y*s.y + sh.y, 0.f) + ev.y;
    r.z = fmaxf(g1.x*s.z + sh.z, 0.f) + ev.z;
    r.w = fmaxf(g1.y*s.w + sh.w, 0.f) + ev.w;
    ((float4*)out)[i] = r;
}

// ---------------- launch -----------------------------------------------------
extern "C" void kernel_launch(void* const* d_in, const int* in_sizes, int n_in,
                              void* d_out, int out_size) {
    const float* h  = (const float*)d_in[0];
    const float* e  = (const float*)d_in[1];
    const float* wA = (const float*)d_in[2];
    const float* wB = (const float*)d_in[3];
    const float* wU = (const float*)d_in[4];
    const float* wV = (const float*)d_in[5];
    const float* wC = (const float*)d_in[6];
    const float* gN = (const float*)d_in[7];
    const float* bN = (const float*)d_in[8];
    const float* gE = (const float*)d_in[9];
    const float* bE = (const float*)d_in[10];
    float* out = (float*)d_out;

    cudaFuncSetAttribute(k_edge_mma, cudaFuncAttributeMaxDynamicSharedMemorySize, SMEM_SZ);

    k_prep<<<512, 256>>>(wC);                               // launch 0
    k_node_gemm<<<dim3(NROWS/16, 4), 128>>>(h, wA, wB, wU, wV);  // launch 1
    k_edge_mma<<<EROWS/128, 256, SMEM_SZ>>>(e);             // launch 2
    k_node_act<<<128, 256>>>();                             // launch 3
    k_stats<<<1, 128>>>(gE, bE, gN, bN);                    // launch 4
    k_hout<<<NROWS*DD/256, 256>>>(h, out);                  // launch 5
    k_eout<<<(EROWS*DD/4)/256, 256>>>(e, out + NROWS*DD);   // launch 6
}